// round 2
// baseline (speedup 1.0000x reference)
#include <cuda_runtime.h>

#define Dm    768
#define Hh    8
#define DKk   96
#define FFm   1024
#define Bbat  8
#define Sseq  1024
#define MR    (Bbat*Sseq)   // 8192 rows
#define BHn   (Bbat*Hh)     // 64 batch*head

// ---------------- scratch (device globals; no allocations allowed) -------------
__device__ float g_q [(size_t)MR*Dm];
__device__ float g_kv[(size_t)MR*Dm];
__device__ float g_sc[(size_t)BHn*Sseq*Sseq];   // 268 MB, T[k,q] layout per (b,h)
__device__ float g_o [(size_t)MR*Dm];
__device__ float g_h [(size_t)MR*FFm];
__device__ float g_x1[(size_t)MR*Dm];
__device__ float g_x2[(size_t)MR*Dm];
__device__ int   g_mask[MR];

// --------- normalize attention_mask (handles int32 OR uint8 storage) -----------
// Deterministic: same input bytes -> same detection -> same output.
__global__ void mask_norm(const unsigned char* __restrict__ raw, int* __restrict__ out)
{
    __shared__ int flag;
    if (threadIdx.x == 0) flag = 0;
    __syncthreads();
    // If stored as little-endian int32 with values 0/1, every byte at offset
    // %4 != 0 is zero. If stored as uint8 bools, ~half of them are 1.
    int local = 0;
    for (int i = threadIdx.x; i < MR; i += blockDim.x)
        if ((i & 3) != 0 && raw[i]) local = 1;
    if (local) flag = 1;
    __syncthreads();
    if (flag) {                      // uint8 bools
        for (int i = threadIdx.x; i < MR; i += blockDim.x)
            out[i] = raw[i] ? 1 : 0;
    } else {                         // int32
        const int* r = (const int*)raw;
        for (int i = threadIdx.x; i < MR; i += blockDim.x)
            out[i] = r[i] ? 1 : 0;
    }
}

// ---------------- generic NN SGEMM: C = A[M,K] @ B[K,N] + bias (opt relu) ------
// M%128==0, N%128==0, K%16==0 (true for all call sites)
__global__ __launch_bounds__(256) void gemm_nn(
    const float* __restrict__ A, const float* __restrict__ B,
    const float* __restrict__ bias, float* __restrict__ C,
    int M, int N, int K, int relu)
{
    __shared__ __align__(16) float As[16][128];
    __shared__ __align__(16) float Bs[16][128];
    const int tid = threadIdx.x;
    const int bm = blockIdx.y * 128;
    const int bn = blockIdx.x * 128;
    const int tr = (tid >> 4) * 8;
    const int tc = (tid & 15) * 8;
    float acc[8][8] = {};
    for (int kt = 0; kt < K; kt += 16) {
        #pragma unroll
        for (int l = 0; l < 2; l++) {
            int f = tid + l * 256;          // 512 float4 for A tile
            int row = f >> 2;
            int cg  = (f & 3) << 2;
            float4 v = *(const float4*)(A + (size_t)(bm + row) * K + kt + cg);
            As[cg + 0][row] = v.x; As[cg + 1][row] = v.y;
            As[cg + 2][row] = v.z; As[cg + 3][row] = v.w;
        }
        #pragma unroll
        for (int l = 0; l < 2; l++) {
            int f = tid + l * 256;          // 512 float4 for B tile
            int row = f >> 5;
            int cg  = (f & 31) << 2;
            *(float4*)&Bs[row][cg] = *(const float4*)(B + (size_t)(kt + row) * N + bn + cg);
        }
        __syncthreads();
        #pragma unroll
        for (int k = 0; k < 16; k++) {
            float a[8], bv[8];
            *(float4*)(a)    = *(float4*)&As[k][tr];
            *(float4*)(a+4)  = *(float4*)&As[k][tr+4];
            *(float4*)(bv)   = *(float4*)&Bs[k][tc];
            *(float4*)(bv+4) = *(float4*)&Bs[k][tc+4];
            #pragma unroll
            for (int i = 0; i < 8; i++)
                #pragma unroll
                for (int j = 0; j < 8; j++)
                    acc[i][j] = fmaf(a[i], bv[j], acc[i][j]);
        }
        __syncthreads();
    }
    #pragma unroll
    for (int i = 0; i < 8; i++) {
        size_t rowoff = (size_t)(bm + tr + i) * N + bn + tc;
        #pragma unroll
        for (int j = 0; j < 8; j += 4) {
            float4 v;
            v.x = acc[i][j+0] + bias[bn+tc+j+0];
            v.y = acc[i][j+1] + bias[bn+tc+j+1];
            v.z = acc[i][j+2] + bias[bn+tc+j+2];
            v.w = acc[i][j+3] + bias[bn+tc+j+3];
            if (relu) {
                v.x = fmaxf(v.x, 0.f); v.y = fmaxf(v.y, 0.f);
                v.z = fmaxf(v.z, 0.f); v.w = fmaxf(v.w, 0.f);
            }
            *(float4*)(C + rowoff + j) = v;
        }
    }
}

// -------- scores (transposed): T[k,q] = KV[k,:]·Q[q,:] / sqrt(DK), masked ------
// grid: (q_tiles=8, k_tiles=8, bh=64)
__global__ __launch_bounds__(256) void scores_nt(
    const float* __restrict__ KVp, const float* __restrict__ Qp,
    const int* __restrict__ pad, float* __restrict__ Sc)
{
    const int bh = blockIdx.z;
    const int b = bh >> 3, h = bh & 7;
    const float* Ab = KVp + (size_t)b * Sseq * Dm + h * DKk;   // k rows, stride Dm
    const float* Bb = Qp  + (size_t)b * Sseq * Dm + h * DKk;   // q rows, stride Dm
    float* Cb = Sc + (size_t)bh * Sseq * Sseq;
    const int* padb = pad + b * Sseq;
    const int bm = blockIdx.y * 128;   // k
    const int bn = blockIdx.x * 128;   // q
    __shared__ __align__(16) float As[16][128];
    __shared__ __align__(16) float Bs[16][128];
    const int tid = threadIdx.x;
    const int tr = (tid >> 4) * 8;
    const int tc = (tid & 15) * 8;
    float acc[8][8] = {};
    for (int kt = 0; kt < DKk; kt += 16) {
        #pragma unroll
        for (int l = 0; l < 2; l++) {
            int f = tid + l * 256;
            int row = f >> 2;
            int cg  = (f & 3) << 2;
            float4 v = *(const float4*)(Ab + (size_t)(bm + row) * Dm + kt + cg);
            As[cg+0][row] = v.x; As[cg+1][row] = v.y;
            As[cg+2][row] = v.z; As[cg+3][row] = v.w;
            float4 w = *(const float4*)(Bb + (size_t)(bn + row) * Dm + kt + cg);
            Bs[cg+0][row] = w.x; Bs[cg+1][row] = w.y;
            Bs[cg+2][row] = w.z; Bs[cg+3][row] = w.w;
        }
        __syncthreads();
        #pragma unroll
        for (int k = 0; k < 16; k++) {
            float a[8], bv[8];
            *(float4*)(a)    = *(float4*)&As[k][tr];
            *(float4*)(a+4)  = *(float4*)&As[k][tr+4];
            *(float4*)(bv)   = *(float4*)&Bs[k][tc];
            *(float4*)(bv+4) = *(float4*)&Bs[k][tc+4];
            #pragma unroll
            for (int i = 0; i < 8; i++)
                #pragma unroll
                for (int j = 0; j < 8; j++)
                    acc[i][j] = fmaf(a[i], bv[j], acc[i][j]);
        }
        __syncthreads();
    }
    const float scale = 0.10206207261596577f;   // 1/sqrt(96)
    int padc[8];
    #pragma unroll
    for (int j = 0; j < 8; j++) padc[j] = padb[bn + tc + j];
    #pragma unroll
    for (int i = 0; i < 8; i++) {
        int krow = bm + tr + i;
        size_t rowoff = (size_t)krow * Sseq + bn + tc;
        #pragma unroll
        for (int j = 0; j < 8; j += 4) {
            float4 v;
            int q0 = bn + tc + j;
            v.x = (q0+0 < krow || padc[j+0]) ? -1e9f : acc[i][j+0]*scale;
            v.y = (q0+1 < krow || padc[j+1]) ? -1e9f : acc[i][j+1]*scale;
            v.z = (q0+2 < krow || padc[j+2]) ? -1e9f : acc[i][j+2]*scale;
            v.w = (q0+3 < krow || padc[j+3]) ? -1e9f : acc[i][j+3]*scale;
            *(float4*)(Cb + rowoff + j) = v;
        }
    }
}

// ---------------- row softmax over q (rows of T), length 1024 ------------------
__global__ __launch_bounds__(256) void softmax_rows(float* __restrict__ sc)
{
    float4* row = (float4*)(sc + (size_t)blockIdx.x * Sseq);
    const int tid = threadIdx.x;
    float4 v = row[tid];
    float m = fmaxf(fmaxf(v.x, v.y), fmaxf(v.z, v.w));
    __shared__ float sh[8];
    #pragma unroll
    for (int o = 16; o > 0; o >>= 1) m = fmaxf(m, __shfl_xor_sync(0xffffffffu, m, o));
    if ((tid & 31) == 0) sh[tid >> 5] = m;
    __syncthreads();
    m = sh[0];
    #pragma unroll
    for (int i = 1; i < 8; i++) m = fmaxf(m, sh[i]);
    float4 e;
    e.x = __expf(v.x - m); e.y = __expf(v.y - m);
    e.z = __expf(v.z - m); e.w = __expf(v.w - m);
    float s = e.x + e.y + e.z + e.w;
    #pragma unroll
    for (int o = 16; o > 0; o >>= 1) s += __shfl_xor_sync(0xffffffffu, s, o);
    __syncthreads();
    if ((tid & 31) == 0) sh[tid >> 5] = s;
    __syncthreads();
    s = 0.f;
    #pragma unroll
    for (int i = 0; i < 8; i++) s += sh[i];
    float inv = 1.0f / s;
    e.x *= inv; e.y *= inv; e.z *= inv; e.w *= inv;
    row[tid] = e;
}

// ---------------- O = T^T @ V  (TN gemm, BM=128, BN=96, BK=16) ------------------
// grid: (q_tiles=8, bh=64)
__global__ __launch_bounds__(256) void out_tn(
    const float* __restrict__ Sc, const float* __restrict__ KVp, float* __restrict__ O)
{
    const int bh = blockIdx.y;
    const int b = bh >> 3, h = bh & 7;
    const float* Ab = Sc  + (size_t)bh * Sseq * Sseq;           // A[k*Sseq + m]
    const float* Bb = KVp + (size_t)b * Sseq * Dm + h * DKk;    // B[k*Dm + n]
    float* Cb = O + (size_t)b * Sseq * Dm + h * DKk;            // C[m*Dm + n]
    const int bm = blockIdx.x * 128;
    __shared__ __align__(16) float As[16][128];
    __shared__ __align__(16) float Bs[16][96];
    const int tid = threadIdx.x;
    const int tr = (tid >> 4) * 8;
    const int tc = (tid & 15) * 6;
    float acc[8][6] = {};
    for (int kt = 0; kt < Sseq; kt += 16) {
        #pragma unroll
        for (int l = 0; l < 2; l++) {
            int f = tid + l * 256;
            int row = f >> 5;
            int cg  = (f & 31) << 2;
            *(float4*)&As[row][cg] = *(const float4*)(Ab + (size_t)(kt + row) * Sseq + bm + cg);
        }
        {
            int f = tid;                          // 384 float4 total for B tile
            int row = f / 24, cg = (f % 24) << 2;
            *(float4*)&Bs[row][cg] = *(const float4*)(Bb + (size_t)(kt + row) * Dm + cg);
            if (tid < 128) {
                f = tid + 256;
                row = f / 24; cg = (f % 24) << 2;
                *(float4*)&Bs[row][cg] = *(const float4*)(Bb + (size_t)(kt + row) * Dm + cg);
            }
        }
        __syncthreads();
        #pragma unroll
        for (int k = 0; k < 16; k++) {
            float a[8], bv[6];
            *(float4*)(a)    = *(float4*)&As[k][tr];
            *(float4*)(a+4)  = *(float4*)&As[k][tr+4];
            *(float2*)(bv)   = *(float2*)&Bs[k][tc];
            *(float2*)(bv+2) = *(float2*)&Bs[k][tc+2];
            *(float2*)(bv+4) = *(float2*)&Bs[k][tc+4];
            #pragma unroll
            for (int i = 0; i < 8; i++)
                #pragma unroll
                for (int j = 0; j < 6; j++)
                    acc[i][j] = fmaf(a[i], bv[j], acc[i][j]);
        }
        __syncthreads();
    }
    #pragma unroll
    for (int i = 0; i < 8; i++) {
        size_t rowoff = (size_t)(bm + tr + i) * Dm + tc;
        #pragma unroll
        for (int j = 0; j < 6; j += 2) {
            float2 v; v.x = acc[i][j]; v.y = acc[i][j+1];
            *(float2*)(Cb + rowoff + j) = v;
        }
    }
}

// ---------------- out = LayerNorm(o + xin) * g + b  (row = 768) -----------------
__global__ __launch_bounds__(256) void add_ln(
    const float* __restrict__ o, const float* __restrict__ xin,
    const float* __restrict__ g, const float* __restrict__ bb,
    float* __restrict__ out)
{
    const size_t base = (size_t)blockIdx.x * Dm;
    const int tid = threadIdx.x;
    float v0 = o[base+tid]       + xin[base+tid];
    float v1 = o[base+tid+256]   + xin[base+tid+256];
    float v2 = o[base+tid+512]   + xin[base+tid+512];
    float s = v0 + v1 + v2;
    float q = v0*v0 + v1*v1 + v2*v2;
    __shared__ float shs[8], shq[8];
    #pragma unroll
    for (int off = 16; off > 0; off >>= 1) {
        s += __shfl_xor_sync(0xffffffffu, s, off);
        q += __shfl_xor_sync(0xffffffffu, q, off);
    }
    if ((tid & 31) == 0) { shs[tid >> 5] = s; shq[tid >> 5] = q; }
    __syncthreads();
    s = 0.f; q = 0.f;
    #pragma unroll
    for (int i = 0; i < 8; i++) { s += shs[i]; q += shq[i]; }
    float mean = s * (1.0f / Dm);
    float var  = q * (1.0f / Dm) - mean * mean;
    float r = rsqrtf(var + 1e-5f);
    out[base+tid]     = (v0 - mean) * r * g[tid]     + bb[tid];
    out[base+tid+256] = (v1 - mean) * r * g[tid+256] + bb[tid+256];
    out[base+tid+512] = (v2 - mean) * r * g[tid+512] + bb[tid+512];
}

// -------------------------------- host orchestration ---------------------------
static void run_mha(const float* xin, float* xout,
                    const float* Wq, const float* bq,
                    const float* Wv, const float* bv,
                    const float* gg, const float* bb,
                    const int* mask,
                    float* q, float* kv, float* sc, float* o)
{
    dim3 gproj(Dm / 128, MR / 128);
    gemm_nn<<<gproj, 256>>>(xin, Wq, bq, q,  MR, Dm, Dm, 0);
    gemm_nn<<<gproj, 256>>>(xin, Wv, bv, kv, MR, Dm, Dm, 0);
    scores_nt<<<dim3(8, 8, BHn), 256>>>(kv, q, mask, sc);
    softmax_rows<<<BHn * Sseq, 256>>>(sc);
    out_tn<<<dim3(8, BHn), 256>>>(sc, kv, o);
    add_ln<<<MR, 256>>>(o, xin, gg, bb, xout);
}

extern "C" void kernel_launch(void* const* d_in, const int* in_sizes, int n_in,
                              void* d_out, int out_size)
{
    const float* x     = (const float*)d_in[0];
    const void*  maskr = d_in[1];
    const float* a1_Wq = (const float*)d_in[2];
    const float* a1_bq = (const float*)d_in[3];
    const float* a1_Wv = (const float*)d_in[4];
    const float* a1_bv = (const float*)d_in[5];
    const float* a1_g  = (const float*)d_in[6];
    const float* a1_b  = (const float*)d_in[7];
    const float* a2_Wq = (const float*)d_in[8];
    const float* a2_bq = (const float*)d_in[9];
    const float* a2_Wv = (const float*)d_in[10];
    const float* a2_bv = (const float*)d_in[11];
    const float* a2_g  = (const float*)d_in[12];
    const float* a2_b  = (const float*)d_in[13];
    const float* f_W1  = (const float*)d_in[14];
    const float* f_b1  = (const float*)d_in[15];
    const float* f_W2  = (const float*)d_in[16];
    const float* f_b2  = (const float*)d_in[17];
    const float* f_g   = (const float*)d_in[18];
    const float* f_b   = (const float*)d_in[19];

    float *q, *kv, *sc, *o, *hbuf, *x1, *x2;
    int *mask;
    cudaGetSymbolAddress((void**)&q,    g_q);
    cudaGetSymbolAddress((void**)&kv,   g_kv);
    cudaGetSymbolAddress((void**)&sc,   g_sc);
    cudaGetSymbolAddress((void**)&o,    g_o);
    cudaGetSymbolAddress((void**)&hbuf, g_h);
    cudaGetSymbolAddress((void**)&x1,   g_x1);
    cudaGetSymbolAddress((void**)&x2,   g_x2);
    cudaGetSymbolAddress((void**)&mask, g_mask);

    mask_norm<<<1, 1024>>>((const unsigned char*)maskr, mask);

    run_mha(x,  x1, a1_Wq, a1_bq, a1_Wv, a1_bv, a1_g, a1_b, mask, q, kv, sc, o);
    run_mha(x1, x2, a2_Wq, a2_bq, a2_Wv, a2_bv, a2_g, a2_b, mask, q, kv, sc, o);

    gemm_nn<<<dim3(FFm / 128, MR / 128), 256>>>(x2, f_W1, f_b1, hbuf, MR, FFm, Dm, 1);
    gemm_nn<<<dim3(Dm  / 128, MR / 128), 256>>>(hbuf, f_W2, f_b2, o,  MR, Dm, FFm, 0);
    add_ln<<<MR, 256>>>(o, x2, f_g, f_b, (float*)d_out);
}

// round 3
// speedup vs baseline: 2.6943x; 2.6943x over previous
#include <cuda_runtime.h>
#include <cstdint>

#define Dm    768
#define Hh    8
#define DKk   96
#define FFm   1024
#define Bbat  8
#define Sseq  1024
#define MR    (Bbat*Sseq)   // 8192 rows
#define BHn   (Bbat*Hh)     // 64 batch*head

// ---------------- scratch (device globals; no allocations allowed) -------------
__device__ float g_q [(size_t)MR*Dm];
__device__ float g_kv[(size_t)MR*Dm];
__device__ float g_sc[(size_t)BHn*Sseq*Sseq];   // 268 MB, T[k,q] layout per (b,h)
__device__ float g_o [(size_t)MR*Dm];
__device__ float g_h [(size_t)MR*FFm];
__device__ float g_x1[(size_t)MR*Dm];
__device__ float g_x2[(size_t)MR*Dm];
__device__ int   g_mask[MR];

// ------------------------------- small helpers ---------------------------------
__device__ __forceinline__ uint32_t f2tf(float x) {
    uint32_t u;
    asm("cvt.rna.tf32.f32 %0, %1;" : "=r"(u) : "f"(x));
    return u;
}

__device__ __forceinline__ void mma8(float* c, const uint32_t* a, const uint32_t* b) {
    asm volatile(
        "mma.sync.aligned.m16n8k8.row.col.f32.tf32.tf32.f32 "
        "{%0,%1,%2,%3}, {%4,%5,%6,%7}, {%8,%9}, {%0,%1,%2,%3};\n"
        : "+f"(c[0]), "+f"(c[1]), "+f"(c[2]), "+f"(c[3])
        : "r"(a[0]), "r"(a[1]), "r"(a[2]), "r"(a[3]), "r"(b[0]), "r"(b[1]));
}

__device__ __forceinline__ void cp16(float* dst_smem, const float* src) {
    uint32_t d = (uint32_t)__cvta_generic_to_shared(dst_smem);
    asm volatile("cp.async.ca.shared.global [%0], [%1], 16;" :: "r"(d), "l"(src));
}
#define CP_COMMIT()  asm volatile("cp.async.commit_group;")
#define CP_WAIT1()   asm volatile("cp.async.wait_group 1;")
#define CP_WAIT0()   asm volatile("cp.async.wait_group 0;")

// --------- normalize attention_mask (handles int32 OR uint8 storage) -----------
__global__ void mask_norm(const unsigned char* __restrict__ raw, int* __restrict__ out)
{
    __shared__ int flag;
    if (threadIdx.x == 0) flag = 0;
    __syncthreads();
    int local = 0;
    for (int i = threadIdx.x; i < MR; i += blockDim.x)
        if ((i & 3) != 0 && raw[i]) local = 1;
    if (local) flag = 1;
    __syncthreads();
    if (flag) {
        for (int i = threadIdx.x; i < MR; i += blockDim.x)
            out[i] = raw[i] ? 1 : 0;
    } else {
        const int* r = (const int*)raw;
        for (int i = threadIdx.x; i < MR; i += blockDim.x)
            out[i] = r[i] ? 1 : 0;
    }
}

// ================= tf32 NN GEMM: C = A[M,K] @ B[K,N] + bias (opt relu) ==========
// block tile 128x128, ktile 32, 256 thr (8 warps, warp tile 64x32), 2-stage cp.async
// smem: As[2][128*32] (m-major, swz (r&7)<<2), Bs[2][32*128] (k-major, swz (k&3)<<3)
__global__ void __launch_bounds__(256) gemm_nn_tf32(
    const float* __restrict__ A, const float* __restrict__ B,
    const float* __restrict__ bias, float* __restrict__ C,
    int M, int N, int K, int relu)
{
    extern __shared__ float sm[];
    float* As = sm;            // 2 * 4096
    float* Bs = sm + 8192;     // 2 * 4096
    const int tid = threadIdx.x;
    const int bm = blockIdx.y * 128, bn = blockIdx.x * 128;
    const int warp = tid >> 5, lane = tid & 31;
    const int u = lane >> 2, cl = lane & 3;
    const int wm = (warp >> 2) * 64, wn = (warp & 3) * 32;
    float acc[4][4][4] = {};
    const int ntile = K >> 5;

    // tile loader
    auto load_tile = [&](int t, int st) {
        const float* Ag = A + (size_t)bm * K + t * 32;
        #pragma unroll
        for (int i = 0; i < 4; i++) {
            int f = tid + i * 256;
            int r = f >> 3, c4 = (f & 7) << 2;
            cp16(&As[st * 4096 + r * 32 + (c4 ^ ((r & 7) << 2))], Ag + (size_t)r * K + c4);
        }
        const float* Bg = B + (size_t)(t * 32) * N + bn;
        #pragma unroll
        for (int i = 0; i < 4; i++) {
            int f = tid + i * 256;
            int k = f >> 5, c4 = (f & 31) << 2;
            cp16(&Bs[st * 4096 + k * 128 + (c4 ^ ((k & 3) << 3))], Bg + (size_t)k * N + c4);
        }
    };

    load_tile(0, 0); CP_COMMIT();
    for (int t = 0; t < ntile; t++) {
        if (t + 1 < ntile) { load_tile(t + 1, (t + 1) & 1); CP_COMMIT(); CP_WAIT1(); }
        else CP_WAIT0();
        __syncthreads();
        const float* Ab = As + (t & 1) * 4096;
        const float* Bb = Bs + (t & 1) * 4096;
        #pragma unroll
        for (int kk = 0; kk < 32; kk += 8) {
            uint32_t af[4][4], bf[4][2];
            #pragma unroll
            for (int mt = 0; mt < 4; mt++) {
                int r = wm + mt * 16 + u;
                int s = (r & 7) << 2;
                af[mt][0] = f2tf(Ab[r * 32 + ((kk + cl) ^ s)]);
                af[mt][1] = f2tf(Ab[(r + 8) * 32 + ((kk + cl) ^ s)]);
                af[mt][2] = f2tf(Ab[r * 32 + ((kk + 4 + cl) ^ s)]);
                af[mt][3] = f2tf(Ab[(r + 8) * 32 + ((kk + 4 + cl) ^ s)]);
            }
            #pragma unroll
            for (int nt = 0; nt < 4; nt++) {
                int n = wn + nt * 8 + u;
                int k0 = kk + cl;
                int s = (k0 & 3) << 3;
                bf[nt][0] = f2tf(Bb[k0 * 128 + (n ^ s)]);
                bf[nt][1] = f2tf(Bb[(k0 + 4) * 128 + (n ^ s)]);
            }
            #pragma unroll
            for (int mt = 0; mt < 4; mt++)
                #pragma unroll
                for (int nt = 0; nt < 4; nt++)
                    mma8(acc[mt][nt], af[mt], bf[nt]);
        }
        __syncthreads();
    }
    // epilogue
    #pragma unroll
    for (int mt = 0; mt < 4; mt++) {
        #pragma unroll
        for (int nt = 0; nt < 4; nt++) {
            int r = bm + wm + mt * 16 + u;
            int c = bn + wn + nt * 8 + 2 * cl;
            float bx = bias[c], by = bias[c + 1];
            float2 v0, v1;
            v0.x = acc[mt][nt][0] + bx; v0.y = acc[mt][nt][1] + by;
            v1.x = acc[mt][nt][2] + bx; v1.y = acc[mt][nt][3] + by;
            if (relu) {
                v0.x = fmaxf(v0.x, 0.f); v0.y = fmaxf(v0.y, 0.f);
                v1.x = fmaxf(v1.x, 0.f); v1.y = fmaxf(v1.y, 0.f);
            }
            *(float2*)(C + (size_t)r * N + c)       = v0;
            *(float2*)(C + (size_t)(r + 8) * N + c) = v1;
        }
    }
}

// ============ tf32 scores: T[k,q] = KV[k,:]·Q[q,:]/sqrt(DK), masked =============
// NT gemm: both operands k-contiguous. block 128(k) x 128(q), ktile 32 over DK=96.
// grid: (q_tiles=8, k_tiles=8, bh=64)
__global__ void __launch_bounds__(256) scores_nt_tf32(
    const float* __restrict__ KVp, const float* __restrict__ Qp,
    const int* __restrict__ pad, float* __restrict__ Sc)
{
    extern __shared__ float sm[];
    float* As = sm;            // KV tile [m128][d32] swz (r&7)<<2, 2 stages
    float* Bs = sm + 8192;     // Q  tile [q128][d32] swz (q&7)<<2, 2 stages
    const int bh = blockIdx.z;
    const int b = bh >> 3, h = bh & 7;
    const float* Ag0 = KVp + (size_t)b * Sseq * Dm + h * DKk;
    const float* Bg0 = Qp  + (size_t)b * Sseq * Dm + h * DKk;
    float* Cb = Sc + (size_t)bh * Sseq * Sseq;
    const int* padb = pad + b * Sseq;
    const int bm = blockIdx.y * 128;   // k rows
    const int bn = blockIdx.x * 128;   // q cols
    const int tid = threadIdx.x;
    const int warp = tid >> 5, lane = tid & 31;
    const int u = lane >> 2, cl = lane & 3;
    const int wm = (warp >> 2) * 64, wn = (warp & 3) * 32;
    float acc[4][4][4] = {};

    auto load_tile = [&](int t, int st) {
        const float* Ag = Ag0 + (size_t)bm * Dm + t * 32;
        const float* Bg = Bg0 + (size_t)bn * Dm + t * 32;
        #pragma unroll
        for (int i = 0; i < 4; i++) {
            int f = tid + i * 256;
            int r = f >> 3, c4 = (f & 7) << 2;
            int off = r * 32 + (c4 ^ ((r & 7) << 2));
            cp16(&As[st * 4096 + off], Ag + (size_t)r * Dm + c4);
            cp16(&Bs[st * 4096 + off], Bg + (size_t)r * Dm + c4);
        }
    };

    load_tile(0, 0); CP_COMMIT();
    for (int t = 0; t < 3; t++) {
        if (t + 1 < 3) { load_tile(t + 1, (t + 1) & 1); CP_COMMIT(); CP_WAIT1(); }
        else CP_WAIT0();
        __syncthreads();
        const float* Ab = As + (t & 1) * 4096;
        const float* Bb = Bs + (t & 1) * 4096;
        #pragma unroll
        for (int kk = 0; kk < 32; kk += 8) {
            uint32_t af[4][4], bf[4][2];
            #pragma unroll
            for (int mt = 0; mt < 4; mt++) {
                int r = wm + mt * 16 + u;
                int s = (r & 7) << 2;
                af[mt][0] = f2tf(Ab[r * 32 + ((kk + cl) ^ s)]);
                af[mt][1] = f2tf(Ab[(r + 8) * 32 + ((kk + cl) ^ s)]);
                af[mt][2] = f2tf(Ab[r * 32 + ((kk + 4 + cl) ^ s)]);
                af[mt][3] = f2tf(Ab[(r + 8) * 32 + ((kk + 4 + cl) ^ s)]);
            }
            #pragma unroll
            for (int nt = 0; nt < 4; nt++) {
                int q = wn + nt * 8 + u;
                int s = (q & 7) << 2;
                bf[nt][0] = f2tf(Bb[q * 32 + ((kk + cl) ^ s)]);
                bf[nt][1] = f2tf(Bb[q * 32 + ((kk + 4 + cl) ^ s)]);
            }
            #pragma unroll
            for (int mt = 0; mt < 4; mt++)
                #pragma unroll
                for (int nt = 0; nt < 4; nt++)
                    mma8(acc[mt][nt], af[mt], bf[nt]);
        }
        __syncthreads();
    }
    const float scale = 0.10206207261596577f;   // 1/sqrt(96)
    #pragma unroll
    for (int mt = 0; mt < 4; mt++) {
        #pragma unroll
        for (int nt = 0; nt < 4; nt++) {
            int kr0 = bm + wm + mt * 16 + u;
            int q0  = bn + wn + nt * 8 + 2 * cl;
            int p0 = padb[q0], p1 = padb[q0 + 1];
            float2 v0, v1;
            v0.x = (q0     < kr0     || p0) ? -1e9f : acc[mt][nt][0] * scale;
            v0.y = (q0 + 1 < kr0     || p1) ? -1e9f : acc[mt][nt][1] * scale;
            v1.x = (q0     < kr0 + 8 || p0) ? -1e9f : acc[mt][nt][2] * scale;
            v1.y = (q0 + 1 < kr0 + 8 || p1) ? -1e9f : acc[mt][nt][3] * scale;
            *(float2*)(Cb + (size_t)kr0 * Sseq + q0)       = v0;
            *(float2*)(Cb + (size_t)(kr0 + 8) * Sseq + q0) = v1;
        }
    }
}

// ---------------- row softmax over q (rows of T), length 1024 ------------------
__global__ void __launch_bounds__(256) softmax_rows(float* __restrict__ sc)
{
    float4* row = (float4*)(sc + (size_t)blockIdx.x * Sseq);
    const int tid = threadIdx.x;
    float4 v = row[tid];
    float m = fmaxf(fmaxf(v.x, v.y), fmaxf(v.z, v.w));
    __shared__ float sh[8];
    #pragma unroll
    for (int o = 16; o > 0; o >>= 1) m = fmaxf(m, __shfl_xor_sync(0xffffffffu, m, o));
    if ((tid & 31) == 0) sh[tid >> 5] = m;
    __syncthreads();
    m = sh[0];
    #pragma unroll
    for (int i = 1; i < 8; i++) m = fmaxf(m, sh[i]);
    float4 e;
    e.x = __expf(v.x - m); e.y = __expf(v.y - m);
    e.z = __expf(v.z - m); e.w = __expf(v.w - m);
    float s = e.x + e.y + e.z + e.w;
    #pragma unroll
    for (int o = 16; o > 0; o >>= 1) s += __shfl_xor_sync(0xffffffffu, s, o);
    __syncthreads();
    if ((tid & 31) == 0) sh[tid >> 5] = s;
    __syncthreads();
    s = 0.f;
    #pragma unroll
    for (int i = 0; i < 8; i++) s += sh[i];
    float inv = 1.0f / s;
    e.x *= inv; e.y *= inv; e.z *= inv; e.w *= inv;
    row[tid] = e;
}

// =================== tf32 O = T^T @ V : block 128(q) x 96(dk) ===================
// A = T tile [k32][q128] (needs "col-major A" -> load fragments transposed)
// B = V tile [k32][n96]. grid: (q_tiles=8, bh=64)
__global__ void __launch_bounds__(256) out_tn_tf32(
    const float* __restrict__ Sc, const float* __restrict__ KVp, float* __restrict__ O)
{
    extern __shared__ float sm[];
    float* As = sm;            // 2 * 4096  ([k][q] swz (k&3)<<3)
    float* Bs = sm + 8192;     // 2 * 3072  ([k][n] swz (k&3)<<3)
    const int bh = blockIdx.y;
    const int b = bh >> 3, h = bh & 7;
    const float* Ag0 = Sc  + (size_t)bh * Sseq * Sseq;
    const float* Bg0 = KVp + (size_t)b * Sseq * Dm + h * DKk;
    float* Cb = O + (size_t)b * Sseq * Dm + h * DKk;
    const int bm = blockIdx.x * 128;
    const int tid = threadIdx.x;
    const int warp = tid >> 5, lane = tid & 31;
    const int u = lane >> 2, cl = lane & 3;
    const int wm = (warp >> 2) * 64, wn = (warp & 3) * 24;
    float acc[4][3][4] = {};

    auto load_tile = [&](int t, int st) {
        const float* Ag = Ag0 + (size_t)(t * 32) * Sseq + bm;
        #pragma unroll
        for (int i = 0; i < 4; i++) {
            int f = tid + i * 256;
            int k = f >> 5, q4 = (f & 31) << 2;
            cp16(&As[st * 4096 + k * 128 + (q4 ^ ((k & 3) << 3))], Ag + (size_t)k * Sseq + q4);
        }
        const float* Bg = Bg0 + (size_t)(t * 32) * Dm;
        #pragma unroll
        for (int i = 0; i < 3; i++) {
            int f = tid + i * 256;
            int k = f / 24, c4 = (f % 24) << 2;
            cp16(&Bs[st * 3072 + k * 96 + (c4 ^ ((k & 3) << 3))], Bg + (size_t)k * Dm + c4);
        }
    };

    load_tile(0, 0); CP_COMMIT();
    for (int t = 0; t < 32; t++) {
        if (t + 1 < 32) { load_tile(t + 1, (t + 1) & 1); CP_COMMIT(); CP_WAIT1(); }
        else CP_WAIT0();
        __syncthreads();
        const float* Ab = As + (t & 1) * 4096;
        const float* Bb = Bs + (t & 1) * 3072;
        #pragma unroll
        for (int kk = 0; kk < 32; kk += 8) {
            uint32_t af[4][4], bf[3][2];
            #pragma unroll
            for (int mt = 0; mt < 4; mt++) {
                int r = wm + mt * 16 + u;        // q index
                int c0 = kk + cl;                // k index
                int s = (c0 & 3) << 3;
                af[mt][0] = f2tf(Ab[c0 * 128 + (r ^ s)]);
                af[mt][1] = f2tf(Ab[c0 * 128 + ((r + 8) ^ s)]);
                af[mt][2] = f2tf(Ab[(c0 + 4) * 128 + (r ^ s)]);
                af[mt][3] = f2tf(Ab[(c0 + 4) * 128 + ((r + 8) ^ s)]);
            }
            #pragma unroll
            for (int nt = 0; nt < 3; nt++) {
                int n = wn + nt * 8 + u;
                int k0 = kk + cl;
                int s = (k0 & 3) << 3;
                bf[nt][0] = f2tf(Bb[k0 * 96 + (n ^ s)]);
                bf[nt][1] = f2tf(Bb[(k0 + 4) * 96 + (n ^ s)]);
            }
            #pragma unroll
            for (int mt = 0; mt < 4; mt++)
                #pragma unroll
                for (int nt = 0; nt < 3; nt++)
                    mma8(acc[mt][nt], af[mt], bf[nt]);
        }
        __syncthreads();
    }
    #pragma unroll
    for (int mt = 0; mt < 4; mt++) {
        #pragma unroll
        for (int nt = 0; nt < 3; nt++) {
            int q = bm + wm + mt * 16 + u;
            int c = wn + nt * 8 + 2 * cl;
            float2 v0, v1;
            v0.x = acc[mt][nt][0]; v0.y = acc[mt][nt][1];
            v1.x = acc[mt][nt][2]; v1.y = acc[mt][nt][3];
            *(float2*)(Cb + (size_t)q * Dm + c)       = v0;
            *(float2*)(Cb + (size_t)(q + 8) * Dm + c) = v1;
        }
    }
}

// ---------------- out = LayerNorm(o + xin) * g + b  (row = 768) -----------------
__global__ void __launch_bounds__(256) add_ln(
    const float* __restrict__ o, const float* __restrict__ xin,
    const float* __restrict__ g, const float* __restrict__ bb,
    float* __restrict__ out)
{
    const size_t base = (size_t)blockIdx.x * Dm;
    const int tid = threadIdx.x;
    float v0 = o[base+tid]       + xin[base+tid];
    float v1 = o[base+tid+256]   + xin[base+tid+256];
    float v2 = o[base+tid+512]   + xin[base+tid+512];
    float s = v0 + v1 + v2;
    float q = v0*v0 + v1*v1 + v2*v2;
    __shared__ float shs[8], shq[8];
    #pragma unroll
    for (int off = 16; off > 0; off >>= 1) {
        s += __shfl_xor_sync(0xffffffffu, s, off);
        q += __shfl_xor_sync(0xffffffffu, q, off);
    }
    if ((tid & 31) == 0) { shs[tid >> 5] = s; shq[tid >> 5] = q; }
    __syncthreads();
    s = 0.f; q = 0.f;
    #pragma unroll
    for (int i = 0; i < 8; i++) { s += shs[i]; q += shq[i]; }
    float mean = s * (1.0f / Dm);
    float var  = q * (1.0f / Dm) - mean * mean;
    float r = rsqrtf(var + 1e-5f);
    out[base+tid]     = (v0 - mean) * r * g[tid]     + bb[tid];
    out[base+tid+256] = (v1 - mean) * r * g[tid+256] + bb[tid+256];
    out[base+tid+512] = (v2 - mean) * r * g[tid+512] + bb[tid+512];
}

// -------------------------------- host orchestration ---------------------------
#define SMEM_GEMM  (16384 * 4)          // 64 KB
#define SMEM_OUT   ((8192 + 6144) * 4)  // 56 KB

static void run_mha(const float* xin, float* xout,
                    const float* Wq, const float* bq,
                    const float* Wv, const float* bv,
                    const float* gg, const float* bb,
                    const int* mask,
                    float* q, float* kv, float* sc, float* o)
{
    dim3 gproj(Dm / 128, MR / 128);
    gemm_nn_tf32<<<gproj, 256, SMEM_GEMM>>>(xin, Wq, bq, q,  MR, Dm, Dm, 0);
    gemm_nn_tf32<<<gproj, 256, SMEM_GEMM>>>(xin, Wv, bv, kv, MR, Dm, Dm, 0);
    scores_nt_tf32<<<dim3(8, 8, BHn), 256, SMEM_GEMM>>>(kv, q, mask, sc);
    softmax_rows<<<BHn * Sseq, 256>>>(sc);
    out_tn_tf32<<<dim3(8, BHn), 256, SMEM_OUT>>>(sc, kv, o);
    add_ln<<<MR, 256>>>(o, xin, gg, bb, xout);
}

extern "C" void kernel_launch(void* const* d_in, const int* in_sizes, int n_in,
                              void* d_out, int out_size)
{
    const float* x     = (const float*)d_in[0];
    const void*  maskr = d_in[1];
    const float* a1_Wq = (const float*)d_in[2];
    const float* a1_bq = (const float*)d_in[3];
    const float* a1_Wv = (const float*)d_in[4];
    const float* a1_bv = (const float*)d_in[5];
    const float* a1_g  = (const float*)d_in[6];
    const float* a1_b  = (const float*)d_in[7];
    const float* a2_Wq = (const float*)d_in[8];
    const float* a2_bq = (const float*)d_in[9];
    const float* a2_Wv = (const float*)d_in[10];
    const float* a2_bv = (const float*)d_in[11];
    const float* a2_g  = (const float*)d_in[12];
    const float* a2_b  = (const float*)d_in[13];
    const float* f_W1  = (const float*)d_in[14];
    const float* f_b1  = (const float*)d_in[15];
    const float* f_W2  = (const float*)d_in[16];
    const float* f_b2  = (const float*)d_in[17];
    const float* f_g   = (const float*)d_in[18];
    const float* f_b   = (const float*)d_in[19];

    static int attr_done = 0;
    if (!attr_done) {
        cudaFuncSetAttribute(gemm_nn_tf32,   cudaFuncAttributeMaxDynamicSharedMemorySize, SMEM_GEMM);
        cudaFuncSetAttribute(scores_nt_tf32, cudaFuncAttributeMaxDynamicSharedMemorySize, SMEM_GEMM);
        cudaFuncSetAttribute(out_tn_tf32,    cudaFuncAttributeMaxDynamicSharedMemorySize, SMEM_OUT);
        attr_done = 1;
    }

    float *q, *kv, *sc, *o, *hbuf, *x1, *x2;
    int *mask;
    cudaGetSymbolAddress((void**)&q,    g_q);
    cudaGetSymbolAddress((void**)&kv,   g_kv);
    cudaGetSymbolAddress((void**)&sc,   g_sc);
    cudaGetSymbolAddress((void**)&o,    g_o);
    cudaGetSymbolAddress((void**)&hbuf, g_h);
    cudaGetSymbolAddress((void**)&x1,   g_x1);
    cudaGetSymbolAddress((void**)&x2,   g_x2);
    cudaGetSymbolAddress((void**)&mask, g_mask);

    mask_norm<<<1, 1024>>>((const unsigned char*)maskr, mask);

    run_mha(x,  x1, a1_Wq, a1_bq, a1_Wv, a1_bv, a1_g, a1_b, mask, q, kv, sc, o);
    run_mha(x1, x2, a2_Wq, a2_bq, a2_Wv, a2_bv, a2_g, a2_b, mask, q, kv, sc, o);

    gemm_nn_tf32<<<dim3(FFm / 128, MR / 128), 256, SMEM_GEMM>>>(x2, f_W1, f_b1, hbuf, MR, FFm, Dm, 1);
    gemm_nn_tf32<<<dim3(Dm  / 128, MR / 128), 256, SMEM_GEMM>>>(hbuf, f_W2, f_b2, o,  MR, Dm, FFm, 0);
    add_ln<<<MR, 256>>>(o, x2, f_g, f_b, (float*)d_out);
}

// round 6
// speedup vs baseline: 2.8909x; 1.0730x over previous
#include <cuda_runtime.h>
#include <cstdint>

#define Dm    768
#define Hh    8
#define DKk   96
#define FFm   1024
#define Bbat  8
#define Sseq  1024
#define MR    (Bbat*Sseq)   // 8192 rows
#define BHn   (Bbat*Hh)     // 64 batch*head

// ---------------- scratch (device globals; no allocations allowed) -------------
__device__ float g_q [(size_t)MR*Dm];
__device__ float g_kv[(size_t)MR*Dm];
__device__ float g_sc[(size_t)BHn*Sseq*Sseq];   // 268 MB, E[k,q] layout per (b,h)
__device__ float g_o [(size_t)MR*Dm];
__device__ float g_h [(size_t)MR*FFm];
__device__ float g_x1[(size_t)MR*Dm];
__device__ float g_x2[(size_t)MR*Dm];
__device__ int   g_mask[MR];
__device__ float g_part[(size_t)BHn*Sseq*8];    // per (bh,k,qtile) partial row sums
__device__ float g_inv [(size_t)BHn*Sseq];      // 1/rowsum (or 1/1024 for dead rows)
__device__ int   g_zfl [(size_t)BHn*Sseq];      // fully-masked-row flag

// ------------------------------- small helpers ---------------------------------
__device__ __forceinline__ uint32_t f2tf(float x) {
    uint32_t u;
    asm("cvt.rna.tf32.f32 %0, %1;" : "=r"(u) : "f"(x));
    return u;
}
__device__ __forceinline__ float rnd_tf(float x) { return __uint_as_float(f2tf(x)); }

__device__ __forceinline__ void mma8(float* c, const uint32_t* a, const uint32_t* b) {
    asm volatile(
        "mma.sync.aligned.m16n8k8.row.col.f32.tf32.tf32.f32 "
        "{%0,%1,%2,%3}, {%4,%5,%6,%7}, {%8,%9}, {%0,%1,%2,%3};\n"
        : "+f"(c[0]), "+f"(c[1]), "+f"(c[2]), "+f"(c[3])
        : "r"(a[0]), "r"(a[1]), "r"(a[2]), "r"(a[3]), "r"(b[0]), "r"(b[1]));
}

__device__ __forceinline__ void cp16(float* dst_smem, const float* src) {
    uint32_t d = (uint32_t)__cvta_generic_to_shared(dst_smem);
    asm volatile("cp.async.ca.shared.global [%0], [%1], 16;" :: "r"(d), "l"(src));
}
#define CP_COMMIT()  asm volatile("cp.async.commit_group;")
#define CP_WAIT1()   asm volatile("cp.async.wait_group 1;")
#define CP_WAIT0()   asm volatile("cp.async.wait_group 0;")

// --------- normalize attention_mask (handles int32 OR uint8 storage) -----------
__global__ void mask_norm(const unsigned char* __restrict__ raw, int* __restrict__ out)
{
    __shared__ int flag;
    if (threadIdx.x == 0) flag = 0;
    __syncthreads();
    int local = 0;
    for (int i = threadIdx.x; i < MR; i += blockDim.x)
        if ((i & 3) != 0 && raw[i]) local = 1;
    if (local) flag = 1;
    __syncthreads();
    if (flag) {
        for (int i = threadIdx.x; i < MR; i += blockDim.x)
            out[i] = raw[i] ? 1 : 0;
    } else {
        const int* r = (const int*)raw;
        for (int i = threadIdx.x; i < MR; i += blockDim.x)
            out[i] = r[i] ? 1 : 0;
    }
}

// ================= tf32 NN GEMM core: C = A[M,K] @ B[K,N] + bias =================
// mode: 0 plain, 1 relu, 2 round-output-to-tf32
__device__ __forceinline__ void gemm_core(
    float* sm, const float* A, const float* B,
    const float* bias, float* C, int M, int N, int K, int mode, int bm, int bn)
{
    float* As = sm;            // 2 * 4096, [m128][k32] swz (r&7)<<2
    float* Bs = sm + 8192;     // 2 * 4096, [k32][n128] swz (k&3)<<3
    const int tid = threadIdx.x;
    const int warp = tid >> 5, lane = tid & 31;
    const int u = lane >> 2, cl = lane & 3;
    const int wm = (warp >> 2) * 64, wn = (warp & 3) * 32;
    float acc[4][4][4] = {};
    const int ntile = K >> 5;

    auto load_tile = [&](int t, int st) {
        const float* Ag = A + (size_t)bm * K + t * 32;
        #pragma unroll
        for (int i = 0; i < 4; i++) {
            int f = tid + i * 256;
            int r = f >> 3, c4 = (f & 7) << 2;
            cp16(&As[st * 4096 + r * 32 + (c4 ^ ((r & 7) << 2))], Ag + (size_t)r * K + c4);
        }
        const float* Bg = B + (size_t)(t * 32) * N + bn;
        #pragma unroll
        for (int i = 0; i < 4; i++) {
            int f = tid + i * 256;
            int k = f >> 5, c4 = (f & 31) << 2;
            cp16(&Bs[st * 4096 + k * 128 + (c4 ^ ((k & 3) << 3))], Bg + (size_t)k * N + c4);
        }
    };

    load_tile(0, 0); CP_COMMIT();
    for (int t = 0; t < ntile; t++) {
        if (t + 1 < ntile) { load_tile(t + 1, (t + 1) & 1); CP_COMMIT(); CP_WAIT1(); }
        else CP_WAIT0();
        __syncthreads();
        const float* Ab = As + (t & 1) * 4096;
        const float* Bb = Bs + (t & 1) * 4096;
        #pragma unroll
        for (int kk = 0; kk < 32; kk += 8) {
            uint32_t af[4][4], bf[4][2];
            #pragma unroll
            for (int mt = 0; mt < 4; mt++) {
                int r = wm + mt * 16 + u;
                int s = (r & 7) << 2;
                af[mt][0] = f2tf(Ab[r * 32 + ((kk + cl) ^ s)]);
                af[mt][1] = f2tf(Ab[(r + 8) * 32 + ((kk + cl) ^ s)]);
                af[mt][2] = f2tf(Ab[r * 32 + ((kk + 4 + cl) ^ s)]);
                af[mt][3] = f2tf(Ab[(r + 8) * 32 + ((kk + 4 + cl) ^ s)]);
            }
            #pragma unroll
            for (int nt = 0; nt < 4; nt++) {
                int n = wn + nt * 8 + u;
                int k0 = kk + cl;
                int s = (k0 & 3) << 3;
                bf[nt][0] = f2tf(Bb[k0 * 128 + (n ^ s)]);
                bf[nt][1] = f2tf(Bb[(k0 + 4) * 128 + (n ^ s)]);
            }
            #pragma unroll
            for (int mt = 0; mt < 4; mt++)
                #pragma unroll
                for (int nt = 0; nt < 4; nt++)
                    mma8(acc[mt][nt], af[mt], bf[nt]);
        }
        __syncthreads();
    }
    #pragma unroll
    for (int mt = 0; mt < 4; mt++) {
        #pragma unroll
        for (int nt = 0; nt < 4; nt++) {
            int r = bm + wm + mt * 16 + u;
            int c = bn + wn + nt * 8 + 2 * cl;
            float bx = bias[c], by = bias[c + 1];
            float2 v0, v1;
            v0.x = acc[mt][nt][0] + bx; v0.y = acc[mt][nt][1] + by;
            v1.x = acc[mt][nt][2] + bx; v1.y = acc[mt][nt][3] + by;
            if (mode == 1) {
                v0.x = fmaxf(v0.x, 0.f); v0.y = fmaxf(v0.y, 0.f);
                v1.x = fmaxf(v1.x, 0.f); v1.y = fmaxf(v1.y, 0.f);
            } else if (mode == 2) {
                v0.x = rnd_tf(v0.x); v0.y = rnd_tf(v0.y);
                v1.x = rnd_tf(v1.x); v1.y = rnd_tf(v1.y);
            }
            *(float2*)(C + (size_t)r * N + c)       = v0;
            *(float2*)(C + (size_t)(r + 8) * N + c) = v1;
        }
    }
}

__global__ void __launch_bounds__(256) gemm_nn_tf32(
    const float* __restrict__ A, const float* __restrict__ B,
    const float* __restrict__ bias, float* __restrict__ C,
    int M, int N, int K, int mode)
{
    extern __shared__ float sm[];
    gemm_core(sm, A, B, bias, C, M, N, K, mode, blockIdx.y * 128, blockIdx.x * 128);
}

// fused Q + KV projection (z selects weight/bias/output), output tf32-rounded
__global__ void __launch_bounds__(256) gemm_proj2(
    const float* __restrict__ x,
    const float* __restrict__ Wq, const float* __restrict__ bq, float* __restrict__ q,
    const float* __restrict__ Wv, const float* __restrict__ bv, float* __restrict__ kv)
{
    extern __shared__ float sm[];
    const float* W = blockIdx.z ? Wv : Wq;
    const float* bb = blockIdx.z ? bv : bq;
    float* C = blockIdx.z ? kv : q;
    gemm_core(sm, x, W, bb, C, MR, Dm, Dm, 2, blockIdx.y * 128, blockIdx.x * 128);
}

// ===== scores: E[k,q] = tf32(exp(KV[k]·Q[q]/sqrt(DK))), masked->0, + row partials
// grid: (q_tiles=8, k_tiles=8, bh=64). operands already tf32-rounded (no cvt).
__global__ void __launch_bounds__(256) scores_exp(
    const float* __restrict__ KVp, const float* __restrict__ Qp,
    const int* __restrict__ pad, float* __restrict__ Sc, float* __restrict__ part_out)
{
    extern __shared__ float sm[];
    float* As = sm;            // KV tile [k128][d32] swz (r&7)<<2, 2 stages
    float* Bs = sm + 8192;     // Q  tile [q128][d32]
    const int bh = blockIdx.z;
    const int b = bh >> 3, h = bh & 7;
    const float* Ag0 = KVp + (size_t)b * Sseq * Dm + h * DKk;
    const float* Bg0 = Qp  + (size_t)b * Sseq * Dm + h * DKk;
    float* Cb = Sc + (size_t)bh * Sseq * Sseq;
    const int* padb = pad + b * Sseq;
    const int bm = blockIdx.y * 128;   // k rows
    const int bn = blockIdx.x * 128;   // q cols
    const int tid = threadIdx.x;
    const int warp = tid >> 5, lane = tid & 31;
    const int u = lane >> 2, cl = lane & 3;
    const int wm = (warp >> 2) * 64, wn = (warp & 3) * 32;
    float acc[4][4][4] = {};

    auto load_tile = [&](int t, int st) {
        const float* Ag = Ag0 + (size_t)bm * Dm + t * 32;
        const float* Bg = Bg0 + (size_t)bn * Dm + t * 32;
        #pragma unroll
        for (int i = 0; i < 4; i++) {
            int f = tid + i * 256;
            int r = f >> 3, c4 = (f & 7) << 2;
            int off = r * 32 + (c4 ^ ((r & 7) << 2));
            cp16(&As[st * 4096 + off], Ag + (size_t)r * Dm + c4);
            cp16(&Bs[st * 4096 + off], Bg + (size_t)r * Dm + c4);
        }
    };

    load_tile(0, 0); CP_COMMIT();
    for (int t = 0; t < 3; t++) {
        if (t + 1 < 3) { load_tile(t + 1, (t + 1) & 1); CP_COMMIT(); CP_WAIT1(); }
        else CP_WAIT0();
        __syncthreads();
        const float* Ab = As + (t & 1) * 4096;
        const float* Bb = Bs + (t & 1) * 4096;
        #pragma unroll
        for (int kk = 0; kk < 32; kk += 8) {
            uint32_t af[4][4], bf[4][2];
            #pragma unroll
            for (int mt = 0; mt < 4; mt++) {
                int r = wm + mt * 16 + u;
                int s = (r & 7) << 2;
                af[mt][0] = __float_as_uint(Ab[r * 32 + ((kk + cl) ^ s)]);
                af[mt][1] = __float_as_uint(Ab[(r + 8) * 32 + ((kk + cl) ^ s)]);
                af[mt][2] = __float_as_uint(Ab[r * 32 + ((kk + 4 + cl) ^ s)]);
                af[mt][3] = __float_as_uint(Ab[(r + 8) * 32 + ((kk + 4 + cl) ^ s)]);
            }
            #pragma unroll
            for (int nt = 0; nt < 4; nt++) {
                int q = wn + nt * 8 + u;
                int s = (q & 7) << 2;
                bf[nt][0] = __float_as_uint(Bb[q * 32 + ((kk + cl) ^ s)]);
                bf[nt][1] = __float_as_uint(Bb[q * 32 + ((kk + 4 + cl) ^ s)]);
            }
            #pragma unroll
            for (int mt = 0; mt < 4; mt++)
                #pragma unroll
                for (int nt = 0; nt < 4; nt++)
                    mma8(acc[mt][nt], af[mt], bf[nt]);
        }
        __syncthreads();
    }

    const float scale = 0.10206207261596577f;   // 1/sqrt(96)
    float rowsum[8] = {};                       // [mt*2 + half]
    #pragma unroll
    for (int mt = 0; mt < 4; mt++) {
        #pragma unroll
        for (int nt = 0; nt < 4; nt++) {
            int kr0 = bm + wm + mt * 16 + u;
            int q0  = bn + wn + nt * 8 + 2 * cl;
            int p0 = padb[q0], p1 = padb[q0 + 1];
            float2 v0, v1;
            v0.x = (q0     < kr0     || p0) ? 0.f : rnd_tf(__expf(acc[mt][nt][0] * scale));
            v0.y = (q0 + 1 < kr0     || p1) ? 0.f : rnd_tf(__expf(acc[mt][nt][1] * scale));
            v1.x = (q0     < kr0 + 8 || p0) ? 0.f : rnd_tf(__expf(acc[mt][nt][2] * scale));
            v1.y = (q0 + 1 < kr0 + 8 || p1) ? 0.f : rnd_tf(__expf(acc[mt][nt][3] * scale));
            rowsum[mt * 2 + 0] += v0.x + v0.y;
            rowsum[mt * 2 + 1] += v1.x + v1.y;
            *(float2*)(Cb + (size_t)kr0 * Sseq + q0)       = v0;
            *(float2*)(Cb + (size_t)(kr0 + 8) * Sseq + q0) = v1;
        }
    }
    // reduce over the 4 cl lanes of the quad (deterministic)
    #pragma unroll
    for (int j = 0; j < 8; j++) {
        rowsum[j] += __shfl_xor_sync(0xffffffffu, rowsum[j], 1);
        rowsum[j] += __shfl_xor_sync(0xffffffffu, rowsum[j], 2);
    }
    float* part = sm;           // alias first 512 floats of tile smem (safe post-sync)
    __syncthreads();
    if (cl == 0) {
        #pragma unroll
        for (int mt = 0; mt < 4; mt++) {
            int lr = wm + mt * 16 + u;
            part[(lr)     * 4 + (warp & 3)] = rowsum[mt * 2 + 0];
            part[(lr + 8) * 4 + (warp & 3)] = rowsum[mt * 2 + 1];
        }
    }
    __syncthreads();
    if (tid < 128) {
        float s = part[tid * 4] + part[tid * 4 + 1] + part[tid * 4 + 2] + part[tid * 4 + 3];
        part_out[((size_t)bh * Sseq + bm + tid) * 8 + blockIdx.x] = s;
    }
}

// ------------- reduce partials -> inv_s, flag fully-masked rows ----------------
__global__ void __launch_bounds__(256) rs_reduce(
    const float* __restrict__ part, float* __restrict__ inv, int* __restrict__ zfl)
{
    int i = blockIdx.x * 256 + threadIdx.x;       // 0 .. BHn*Sseq-1
    float s = 0.f;
    #pragma unroll
    for (int j = 0; j < 8; j++) s += part[(size_t)i * 8 + j];
    if (s == 0.f) { inv[i] = 1.0f / 1024.0f; zfl[i] = 1; }
    else          { inv[i] = 1.0f / s;       zfl[i] = 0; }
}

// ---- rewrite fully-masked E rows to all-ones (reference: uniform softmax) -----
__global__ void __launch_bounds__(256) zero_fix(
    const int* __restrict__ zfl, float* __restrict__ E)
{
    int bh = blockIdx.x;
    for (int k = 0; k < Sseq; k++) {
        if (zfl[bh * Sseq + k]) {
            float4* row = (float4*)(E + ((size_t)bh * Sseq + k) * Sseq);
            for (int q = threadIdx.x; q < Sseq / 4; q += 256)
                row[q] = make_float4(1.f, 1.f, 1.f, 1.f);
        }
    }
}

// =================== O = E^T @ (inv_s * V) : block 128(q) x 96(dk) ==============
// grid: (q_tiles=8, bh=64). E, V already tf32-rounded; scale V-fragments by inv_s.
__global__ void __launch_bounds__(256) out_tn_tf32(
    const float* __restrict__ Sc, const float* __restrict__ KVp,
    const float* __restrict__ inv, float* __restrict__ O)
{
    extern __shared__ float sm[];
    float* As = sm;            // 2 * 4096  ([k32][q128] swz (k&3)<<3)
    float* Bs = sm + 8192;     // 2 * 3072  ([k32][n96]  swz (k&3)<<3)
    float* Is = sm + 14336;    // 2 * 32    inv_s per tile
    const int bh = blockIdx.y;
    const int b = bh >> 3, h = bh & 7;
    const float* Ag0 = Sc  + (size_t)bh * Sseq * Sseq;
    const float* Bg0 = KVp + (size_t)b * Sseq * Dm + h * DKk;
    const float* inv0 = inv + (size_t)bh * Sseq;
    float* Cb = O + (size_t)b * Sseq * Dm + h * DKk;
    const int bm = blockIdx.x * 128;
    const int tid = threadIdx.x;
    const int warp = tid >> 5, lane = tid & 31;
    const int u = lane >> 2, cl = lane & 3;
    const int wm = (warp >> 2) * 64, wn = (warp & 3) * 24;
    float acc[4][3][4] = {};

    auto load_tile = [&](int t, int st) {
        const float* Ag = Ag0 + (size_t)(t * 32) * Sseq + bm;
        #pragma unroll
        for (int i = 0; i < 4; i++) {
            int f = tid + i * 256;
            int k = f >> 5, q4 = (f & 31) << 2;
            cp16(&As[st * 4096 + k * 128 + (q4 ^ ((k & 3) << 3))], Ag + (size_t)k * Sseq + q4);
        }
        const float* Bg = Bg0 + (size_t)(t * 32) * Dm;
        #pragma unroll
        for (int i = 0; i < 3; i++) {
            int f = tid + i * 256;
            int k = f / 24, c4 = (f % 24) << 2;
            cp16(&Bs[st * 3072 + k * 96 + (c4 ^ ((k & 3) << 3))], Bg + (size_t)k * Dm + c4);
        }
        if (tid < 8) cp16(&Is[st * 32 + tid * 4], inv0 + t * 32 + tid * 4);
    };

    load_tile(0, 0); CP_COMMIT();
    for (int t = 0; t < 32; t++) {
        if (t + 1 < 32) { load_tile(t + 1, (t + 1) & 1); CP_COMMIT(); CP_WAIT1(); }
        else CP_WAIT0();
        __syncthreads();
        const float* Ab = As + (t & 1) * 4096;
        const float* Bb = Bs + (t & 1) * 3072;
        const float* Ib = Is + (t & 1) * 32;
        #pragma unroll
        for (int kk = 0; kk < 32; kk += 8) {
            uint32_t af[4][4], bf[3][2];
            int k0 = kk + cl;
            float is0 = Ib[k0], is1 = Ib[k0 + 4];
            int s = (k0 & 3) << 3;
            #pragma unroll
            for (int mt = 0; mt < 4; mt++) {
                int r = wm + mt * 16 + u;        // q index
                af[mt][0] = __float_as_uint(Ab[k0 * 128 + (r ^ s)]);
                af[mt][1] = __float_as_uint(Ab[k0 * 128 + ((r + 8) ^ s)]);
                af[mt][2] = __float_as_uint(Ab[(k0 + 4) * 128 + (r ^ s)]);
                af[mt][3] = __float_as_uint(Ab[(k0 + 4) * 128 + ((r + 8) ^ s)]);
            }
            #pragma unroll
            for (int nt = 0; nt < 3; nt++) {
                int n = wn + nt * 8 + u;
                bf[nt][0] = f2tf(Bb[k0 * 96 + (n ^ s)] * is0);
                bf[nt][1] = f2tf(Bb[(k0 + 4) * 96 + (n ^ s)] * is1);
            }
            #pragma unroll
            for (int mt = 0; mt < 4; mt++)
                #pragma unroll
                for (int nt = 0; nt < 3; nt++)
                    mma8(acc[mt][nt], af[mt], bf[nt]);
        }
        __syncthreads();
    }
    #pragma unroll
    for (int mt = 0; mt < 4; mt++) {
        #pragma unroll
        for (int nt = 0; nt < 3; nt++) {
            int q = bm + wm + mt * 16 + u;
            int c = wn + nt * 8 + 2 * cl;
            float2 v0, v1;
            v0.x = acc[mt][nt][0]; v0.y = acc[mt][nt][1];
            v1.x = acc[mt][nt][2]; v1.y = acc[mt][nt][3];
            *(float2*)(Cb + (size_t)q * Dm + c)       = v0;
            *(float2*)(Cb + (size_t)(q + 8) * Dm + c) = v1;
        }
    }
}

// ---------------- out = LayerNorm(o + xin) * g + b  (row = 768) -----------------
__global__ void __launch_bounds__(256) add_ln(
    const float* __restrict__ o, const float* __restrict__ xin,
    const float* __restrict__ g, const float* __restrict__ bb,
    float* __restrict__ out)
{
    const size_t base = (size_t)blockIdx.x * Dm;
    const int tid = threadIdx.x;
    float v0 = o[base+tid]       + xin[base+tid];
    float v1 = o[base+tid+256]   + xin[base+tid+256];
    float v2 = o[base+tid+512]   + xin[base+tid+512];
    float s = v0 + v1 + v2;
    float q = v0*v0 + v1*v1 + v2*v2;
    __shared__ float shs[8], shq[8];
    #pragma unroll
    for (int off = 16; off > 0; off >>= 1) {
        s += __shfl_xor_sync(0xffffffffu, s, off);
        q += __shfl_xor_sync(0xffffffffu, q, off);
    }
    if ((tid & 31) == 0) { shs[tid >> 5] = s; shq[tid >> 5] = q; }
    __syncthreads();
    s = 0.f; q = 0.f;
    #pragma unroll
    for (int i = 0; i < 8; i++) { s += shs[i]; q += shq[i]; }
    float mean = s * (1.0f / Dm);
    float var  = q * (1.0f / Dm) - mean * mean;
    float r = rsqrtf(var + 1e-5f);
    out[base+tid]     = (v0 - mean) * r * g[tid]     + bb[tid];
    out[base+tid+256] = (v1 - mean) * r * g[tid+256] + bb[tid+256];
    out[base+tid+512] = (v2 - mean) * r * g[tid+512] + bb[tid+512];
}

// -------------------------------- host orchestration ---------------------------
#define SMEM_GEMM  (16384 * 4)          // 64 KB
#define SMEM_OUT   (14400 * 4)          // 57.6 KB

static void run_mha(const float* xin, float* xout,
                    const float* Wq, const float* bq,
                    const float* Wv, const float* bv,
                    const float* gg, const float* bb,
                    const int* mask,
                    float* q, float* kv, float* sc, float* o,
                    float* part, float* inv, int* zfl)
{
    gemm_proj2<<<dim3(Dm / 128, MR / 128, 2), 256, SMEM_GEMM>>>(xin, Wq, bq, q, Wv, bv, kv);
    scores_exp<<<dim3(8, 8, BHn), 256, SMEM_GEMM>>>(kv, q, mask, sc, part);
    rs_reduce<<<BHn * Sseq / 256, 256>>>(part, inv, zfl);
    zero_fix<<<BHn, 256>>>(zfl, sc);
    out_tn_tf32<<<dim3(8, BHn), 256, SMEM_OUT>>>(sc, kv, inv, o);
    add_ln<<<MR, 256>>>(o, xin, gg, bb, xout);
}

extern "C" void kernel_launch(void* const* d_in, const int* in_sizes, int n_in,
                              void* d_out, int out_size)
{
    const float* x     = (const float*)d_in[0];
    const void*  maskr = d_in[1];
    const float* a1_Wq = (const float*)d_in[2];
    const float* a1_bq = (const float*)d_in[3];
    const float* a1_Wv = (const float*)d_in[4];
    const float* a1_bv = (const float*)d_in[5];
    const float* a1_g  = (const float*)d_in[6];
    const float* a1_b  = (const float*)d_in[7];
    const float* a2_Wq = (const float*)d_in[8];
    const float* a2_bq = (const float*)d_in[9];
    const float* a2_Wv = (const float*)d_in[10];
    const float* a2_bv = (const float*)d_in[11];
    const float* a2_g  = (const float*)d_in[12];
    const float* a2_b  = (const float*)d_in[13];
    const float* f_W1  = (const float*)d_in[14];
    const float* f_b1  = (const float*)d_in[15];
    const float* f_W2  = (const float*)d_in[16];
    const float* f_b2  = (const float*)d_in[17];
    const float* f_g   = (const float*)d_in[18];
    const float* f_b   = (const float*)d_in[19];

    static int attr_done = 0;
    if (!attr_done) {
        cudaFuncSetAttribute(gemm_nn_tf32, cudaFuncAttributeMaxDynamicSharedMemorySize, SMEM_GEMM);
        cudaFuncSetAttribute(gemm_proj2,   cudaFuncAttributeMaxDynamicSharedMemorySize, SMEM_GEMM);
        cudaFuncSetAttribute(scores_exp,   cudaFuncAttributeMaxDynamicSharedMemorySize, SMEM_GEMM);
        cudaFuncSetAttribute(out_tn_tf32,  cudaFuncAttributeMaxDynamicSharedMemorySize, SMEM_OUT);
        attr_done = 1;
    }

    float *q, *kv, *sc, *o, *hbuf, *x1, *x2, *part, *inv;
    int *mask, *zfl;
    cudaGetSymbolAddress((void**)&q,    g_q);
    cudaGetSymbolAddress((void**)&kv,   g_kv);
    cudaGetSymbolAddress((void**)&sc,   g_sc);
    cudaGetSymbolAddress((void**)&o,    g_o);
    cudaGetSymbolAddress((void**)&hbuf, g_h);
    cudaGetSymbolAddress((void**)&x1,   g_x1);
    cudaGetSymbolAddress((void**)&x2,   g_x2);
    cudaGetSymbolAddress((void**)&mask, g_mask);
    cudaGetSymbolAddress((void**)&part, g_part);
    cudaGetSymbolAddress((void**)&inv,  g_inv);
    cudaGetSymbolAddress((void**)&zfl,  g_zfl);

    mask_norm<<<1, 1024>>>((const unsigned char*)maskr, mask);

    run_mha(x,  x1, a1_Wq, a1_bq, a1_Wv, a1_bv, a1_g, a1_b, mask, q, kv, sc, o, part, inv, zfl);
    run_mha(x1, x2, a2_Wq, a2_bq, a2_Wv, a2_bv, a2_g, a2_b, mask, q, kv, sc, o, part, inv, zfl);

    gemm_nn_tf32<<<dim3(FFm / 128, MR / 128), 256, SMEM_GEMM>>>(x2, f_W1, f_b1, hbuf, MR, FFm, Dm, 1);
    gemm_nn_tf32<<<dim3(Dm  / 128, MR / 128), 256, SMEM_GEMM>>>(hbuf, f_W2, f_b2, o,  MR, Dm, FFm, 0);
    add_ln<<<MR, 256>>>(o, x2, f_g, f_b, (float*)d_out);
}

// round 7
// speedup vs baseline: 3.1865x; 1.1022x over previous
#include <cuda_runtime.h>
#include <cuda_bf16.h>
#include <cstdint>

#define Dm    768
#define Hh    8
#define DKk   96
#define FFm   1024
#define Bbat  8
#define Sseq  1024
#define MR    (Bbat*Sseq)   // 8192 rows
#define BHn   (Bbat*Hh)     // 64 batch*head

// ---------------- scratch (device globals; no allocations allowed) -------------
__device__ float g_q [(size_t)MR*Dm];
__device__ float g_kv[(size_t)MR*Dm];
__device__ __nv_bfloat16 g_sc[(size_t)BHn*Sseq*Sseq];   // 134 MB, E[k,q] bf16
__device__ float g_o [(size_t)MR*Dm];
__device__ float g_h [(size_t)MR*FFm];
__device__ float g_x1[(size_t)MR*Dm];
__device__ float g_x2[(size_t)MR*Dm];
__device__ int   g_mask[MR];
__device__ float g_part[(size_t)BHn*Sseq*8];    // per (bh,k,qtile) partial row sums
__device__ float g_inv [(size_t)BHn*Sseq];      // 1/rowsum (or 1/1024 for dead rows)

// ------------------------------- small helpers ---------------------------------
__device__ __forceinline__ uint32_t f2tf(float x) {
    uint32_t u;
    asm("cvt.rna.tf32.f32 %0, %1;" : "=r"(u) : "f"(x));
    return u;
}
__device__ __forceinline__ float rnd_tf(float x) { return __uint_as_float(f2tf(x)); }

__device__ __forceinline__ void mma8(float* c, const uint32_t* a, const uint32_t* b) {
    asm volatile(
        "mma.sync.aligned.m16n8k8.row.col.f32.tf32.tf32.f32 "
        "{%0,%1,%2,%3}, {%4,%5,%6,%7}, {%8,%9}, {%0,%1,%2,%3};\n"
        : "+f"(c[0]), "+f"(c[1]), "+f"(c[2]), "+f"(c[3])
        : "r"(a[0]), "r"(a[1]), "r"(a[2]), "r"(a[3]), "r"(b[0]), "r"(b[1]));
}

__device__ __forceinline__ void cp16(void* dst_smem, const void* src) {
    uint32_t d = (uint32_t)__cvta_generic_to_shared(dst_smem);
    asm volatile("cp.async.ca.shared.global [%0], [%1], 16;" :: "r"(d), "l"(src));
}
#define CP_COMMIT()  asm volatile("cp.async.commit_group;")
#define CP_WAIT1()   asm volatile("cp.async.wait_group 1;")
#define CP_WAIT0()   asm volatile("cp.async.wait_group 0;")

// --------- normalize attention_mask (handles int32 OR uint8 storage) -----------
__global__ void mask_norm(const unsigned char* __restrict__ raw, int* __restrict__ out)
{
    __shared__ int flag;
    if (threadIdx.x == 0) flag = 0;
    __syncthreads();
    int local = 0;
    for (int i = threadIdx.x; i < MR; i += blockDim.x)
        if ((i & 3) != 0 && raw[i]) local = 1;
    if (local) flag = 1;
    __syncthreads();
    if (flag) {
        for (int i = threadIdx.x; i < MR; i += blockDim.x)
            out[i] = raw[i] ? 1 : 0;
    } else {
        const int* r = (const int*)raw;
        for (int i = threadIdx.x; i < MR; i += blockDim.x)
            out[i] = r[i] ? 1 : 0;
    }
}

// ================= tf32 NN GEMM core: C = A[M,K] @ B[K,N] + bias =================
// mode: 0 plain, 1 relu, 2 round-output-to-tf32
__device__ __forceinline__ void gemm_core(
    float* sm, const float* A, const float* B,
    const float* bias, float* C, int M, int N, int K, int mode, int bm, int bn)
{
    float* As = sm;            // 2 * 4096, [m128][k32] swz (r&7)<<2
    float* Bs = sm + 8192;     // 2 * 4096, [k32][n128] swz (k&3)<<3
    const int tid = threadIdx.x;
    const int warp = tid >> 5, lane = tid & 31;
    const int u = lane >> 2, cl = lane & 3;
    const int wm = (warp >> 2) * 64, wn = (warp & 3) * 32;
    float acc[4][4][4] = {};
    const int ntile = K >> 5;

    auto load_tile = [&](int t, int st) {
        const float* Ag = A + (size_t)bm * K + t * 32;
        #pragma unroll
        for (int i = 0; i < 4; i++) {
            int f = tid + i * 256;
            int r = f >> 3, c4 = (f & 7) << 2;
            cp16(&As[st * 4096 + r * 32 + (c4 ^ ((r & 7) << 2))], Ag + (size_t)r * K + c4);
        }
        const float* Bg = B + (size_t)(t * 32) * N + bn;
        #pragma unroll
        for (int i = 0; i < 4; i++) {
            int f = tid + i * 256;
            int k = f >> 5, c4 = (f & 31) << 2;
            cp16(&Bs[st * 4096 + k * 128 + (c4 ^ ((k & 3) << 3))], Bg + (size_t)k * N + c4);
        }
    };

    load_tile(0, 0); CP_COMMIT();
    for (int t = 0; t < ntile; t++) {
        if (t + 1 < ntile) { load_tile(t + 1, (t + 1) & 1); CP_COMMIT(); CP_WAIT1(); }
        else CP_WAIT0();
        __syncthreads();
        const float* Ab = As + (t & 1) * 4096;
        const float* Bb = Bs + (t & 1) * 4096;
        #pragma unroll
        for (int kk = 0; kk < 32; kk += 8) {
            uint32_t af[4][4], bf[4][2];
            #pragma unroll
            for (int mt = 0; mt < 4; mt++) {
                int r = wm + mt * 16 + u;
                int s = (r & 7) << 2;
                af[mt][0] = f2tf(Ab[r * 32 + ((kk + cl) ^ s)]);
                af[mt][1] = f2tf(Ab[(r + 8) * 32 + ((kk + cl) ^ s)]);
                af[mt][2] = f2tf(Ab[r * 32 + ((kk + 4 + cl) ^ s)]);
                af[mt][3] = f2tf(Ab[(r + 8) * 32 + ((kk + 4 + cl) ^ s)]);
            }
            #pragma unroll
            for (int nt = 0; nt < 4; nt++) {
                int n = wn + nt * 8 + u;
                int k0 = kk + cl;
                int s = (k0 & 3) << 3;
                bf[nt][0] = f2tf(Bb[k0 * 128 + (n ^ s)]);
                bf[nt][1] = f2tf(Bb[(k0 + 4) * 128 + (n ^ s)]);
            }
            #pragma unroll
            for (int mt = 0; mt < 4; mt++)
                #pragma unroll
                for (int nt = 0; nt < 4; nt++)
                    mma8(acc[mt][nt], af[mt], bf[nt]);
        }
        __syncthreads();
    }
    #pragma unroll
    for (int mt = 0; mt < 4; mt++) {
        #pragma unroll
        for (int nt = 0; nt < 4; nt++) {
            int r = bm + wm + mt * 16 + u;
            int c = bn + wn + nt * 8 + 2 * cl;
            float bx = bias[c], by = bias[c + 1];
            float2 v0, v1;
            v0.x = acc[mt][nt][0] + bx; v0.y = acc[mt][nt][1] + by;
            v1.x = acc[mt][nt][2] + bx; v1.y = acc[mt][nt][3] + by;
            if (mode == 1) {
                v0.x = fmaxf(v0.x, 0.f); v0.y = fmaxf(v0.y, 0.f);
                v1.x = fmaxf(v1.x, 0.f); v1.y = fmaxf(v1.y, 0.f);
            } else if (mode == 2) {
                v0.x = rnd_tf(v0.x); v0.y = rnd_tf(v0.y);
                v1.x = rnd_tf(v1.x); v1.y = rnd_tf(v1.y);
            }
            *(float2*)(C + (size_t)r * N + c)       = v0;
            *(float2*)(C + (size_t)(r + 8) * N + c) = v1;
        }
    }
}

__global__ void __launch_bounds__(256) gemm_nn_tf32(
    const float* __restrict__ A, const float* __restrict__ B,
    const float* __restrict__ bias, float* __restrict__ C,
    int M, int N, int K, int mode)
{
    extern __shared__ float sm[];
    gemm_core(sm, A, B, bias, C, M, N, K, mode, blockIdx.y * 128, blockIdx.x * 128);
}

// fused Q + KV projection (z selects weight/bias/output), output tf32-rounded
__global__ void __launch_bounds__(256) gemm_proj2(
    const float* __restrict__ x,
    const float* __restrict__ Wq, const float* __restrict__ bq, float* __restrict__ q,
    const float* __restrict__ Wv, const float* __restrict__ bv, float* __restrict__ kv)
{
    extern __shared__ float sm[];
    const float* W = blockIdx.z ? Wv : Wq;
    const float* bb = blockIdx.z ? bv : bq;
    float* C = blockIdx.z ? kv : q;
    gemm_core(sm, x, W, bb, C, MR, Dm, Dm, 2, blockIdx.y * 128, blockIdx.x * 128);
}

// ===== scores: E[k,q] = bf16(exp(KV[k]·Q[q]/sqrt(DK))), masked->0, + row partials
// grid: (q_tiles=8, k_tiles=8, bh=64). operands already tf32-rounded (no cvt).
__global__ void __launch_bounds__(256) scores_exp(
    const float* __restrict__ KVp, const float* __restrict__ Qp,
    const int* __restrict__ pad, __nv_bfloat16* __restrict__ Sc,
    float* __restrict__ part_out)
{
    extern __shared__ float sm[];
    float* As = sm;            // KV tile [k128][d32] swz (r&7)<<2, 2 stages
    float* Bs = sm + 8192;     // Q  tile [q128][d32]
    const int bh = blockIdx.z;
    const int b = bh >> 3, h = bh & 7;
    const float* Ag0 = KVp + (size_t)b * Sseq * Dm + h * DKk;
    const float* Bg0 = Qp  + (size_t)b * Sseq * Dm + h * DKk;
    __nv_bfloat16* Cb = Sc + (size_t)bh * Sseq * Sseq;
    const int* padb = pad + b * Sseq;
    const int bm = blockIdx.y * 128;   // k rows
    const int bn = blockIdx.x * 128;   // q cols
    const int tid = threadIdx.x;
    const int warp = tid >> 5, lane = tid & 31;
    const int u = lane >> 2, cl = lane & 3;
    const int wm = (warp >> 2) * 64, wn = (warp & 3) * 32;
    float acc[4][4][4] = {};

    auto load_tile = [&](int t, int st) {
        const float* Ag = Ag0 + (size_t)bm * Dm + t * 32;
        const float* Bg = Bg0 + (size_t)bn * Dm + t * 32;
        #pragma unroll
        for (int i = 0; i < 4; i++) {
            int f = tid + i * 256;
            int r = f >> 3, c4 = (f & 7) << 2;
            int off = r * 32 + (c4 ^ ((r & 7) << 2));
            cp16(&As[st * 4096 + off], Ag + (size_t)r * Dm + c4);
            cp16(&Bs[st * 4096 + off], Bg + (size_t)r * Dm + c4);
        }
    };

    load_tile(0, 0); CP_COMMIT();
    for (int t = 0; t < 3; t++) {
        if (t + 1 < 3) { load_tile(t + 1, (t + 1) & 1); CP_COMMIT(); CP_WAIT1(); }
        else CP_WAIT0();
        __syncthreads();
        const float* Ab = As + (t & 1) * 4096;
        const float* Bb = Bs + (t & 1) * 4096;
        #pragma unroll
        for (int kk = 0; kk < 32; kk += 8) {
            uint32_t af[4][4], bf[4][2];
            #pragma unroll
            for (int mt = 0; mt < 4; mt++) {
                int r = wm + mt * 16 + u;
                int s = (r & 7) << 2;
                af[mt][0] = __float_as_uint(Ab[r * 32 + ((kk + cl) ^ s)]);
                af[mt][1] = __float_as_uint(Ab[(r + 8) * 32 + ((kk + cl) ^ s)]);
                af[mt][2] = __float_as_uint(Ab[r * 32 + ((kk + 4 + cl) ^ s)]);
                af[mt][3] = __float_as_uint(Ab[(r + 8) * 32 + ((kk + 4 + cl) ^ s)]);
            }
            #pragma unroll
            for (int nt = 0; nt < 4; nt++) {
                int q = wn + nt * 8 + u;
                int s = (q & 7) << 2;
                bf[nt][0] = __float_as_uint(Bb[q * 32 + ((kk + cl) ^ s)]);
                bf[nt][1] = __float_as_uint(Bb[q * 32 + ((kk + 4 + cl) ^ s)]);
            }
            #pragma unroll
            for (int mt = 0; mt < 4; mt++)
                #pragma unroll
                for (int nt = 0; nt < 4; nt++)
                    mma8(acc[mt][nt], af[mt], bf[nt]);
        }
        __syncthreads();
    }

    const float scale = 0.10206207261596577f;   // 1/sqrt(96)
    float rowsum[8] = {};                       // [mt*2 + half]
    #pragma unroll
    for (int mt = 0; mt < 4; mt++) {
        #pragma unroll
        for (int nt = 0; nt < 4; nt++) {
            int kr0 = bm + wm + mt * 16 + u;
            int q0  = bn + wn + nt * 8 + 2 * cl;
            int p0 = padb[q0], p1 = padb[q0 + 1];
            float e00 = (q0     < kr0     || p0) ? 0.f : __expf(acc[mt][nt][0] * scale);
            float e01 = (q0 + 1 < kr0     || p1) ? 0.f : __expf(acc[mt][nt][1] * scale);
            float e10 = (q0     < kr0 + 8 || p0) ? 0.f : __expf(acc[mt][nt][2] * scale);
            float e11 = (q0 + 1 < kr0 + 8 || p1) ? 0.f : __expf(acc[mt][nt][3] * scale);
            __nv_bfloat162 w0, w1;
            w0.x = __float2bfloat16(e00); w0.y = __float2bfloat16(e01);
            w1.x = __float2bfloat16(e10); w1.y = __float2bfloat16(e11);
            rowsum[mt * 2 + 0] += __bfloat162float(w0.x) + __bfloat162float(w0.y);
            rowsum[mt * 2 + 1] += __bfloat162float(w1.x) + __bfloat162float(w1.y);
            *(__nv_bfloat162*)(Cb + (size_t)kr0 * Sseq + q0)       = w0;
            *(__nv_bfloat162*)(Cb + (size_t)(kr0 + 8) * Sseq + q0) = w1;
        }
    }
    // reduce over the 4 cl lanes of the quad (deterministic)
    #pragma unroll
    for (int j = 0; j < 8; j++) {
        rowsum[j] += __shfl_xor_sync(0xffffffffu, rowsum[j], 1);
        rowsum[j] += __shfl_xor_sync(0xffffffffu, rowsum[j], 2);
    }
    float* part = sm;           // alias tile smem (safe post-sync)
    __syncthreads();
    if (cl == 0) {
        #pragma unroll
        for (int mt = 0; mt < 4; mt++) {
            int lr = wm + mt * 16 + u;
            part[(lr)     * 4 + (warp & 3)] = rowsum[mt * 2 + 0];
            part[(lr + 8) * 4 + (warp & 3)] = rowsum[mt * 2 + 1];
        }
    }
    __syncthreads();
    if (tid < 128) {
        float s = part[tid * 4] + part[tid * 4 + 1] + part[tid * 4 + 2] + part[tid * 4 + 3];
        part_out[((size_t)bh * Sseq + bm + tid) * 8 + blockIdx.x] = s;
    }
}

// ------ reduce partials -> inv_s; rewrite dead E rows to 1 (uniform softmax) ----
__global__ void __launch_bounds__(256) rs_reduce_fix(
    const float* __restrict__ part, float* __restrict__ inv, __nv_bfloat16* __restrict__ E)
{
    int i = blockIdx.x * 256 + threadIdx.x;       // 0 .. BHn*Sseq-1  (= bh*Sseq + k)
    float s = 0.f;
    #pragma unroll
    for (int j = 0; j < 8; j++) s += part[(size_t)i * 8 + j];
    if (s == 0.f) {
        inv[i] = 1.0f / 1024.0f;
        uint4* row = (uint4*)(E + (size_t)i * Sseq);
        uint4 ones = make_uint4(0x3F803F80u, 0x3F803F80u, 0x3F803F80u, 0x3F803F80u);
        for (int j = 0; j < Sseq / 8; j++) row[j] = ones;   // rare path
    } else {
        inv[i] = 1.0f / s;
    }
}

// =============== O = E^T @ (inv_s * V) : block 128(q) x 96(dk), E bf16 ==========
// grid: (q_tiles=8, bh=64). E bf16 -> tf32 via <<16 (exact); V already tf32.
__global__ void __launch_bounds__(256) out_tn_tf32(
    const __nv_bfloat16* __restrict__ Sc, const float* __restrict__ KVp,
    const float* __restrict__ inv, float* __restrict__ O)
{
    extern __shared__ float sm[];
    float* As = sm;            // 2 stages * 2048 floats (=32k x 128q bf16, unit-swz)
    float* Bs = sm + 4096;     // 2 * 3072  ([k32][n96] swz (k&3)<<3)
    float* Is = sm + 10240;    // 2 * 32    inv_s per tile
    const int bh = blockIdx.y;
    const int b = bh >> 3, h = bh & 7;
    const __nv_bfloat16* Ag0 = Sc + (size_t)bh * Sseq * Sseq;
    const float* Bg0 = KVp + (size_t)b * Sseq * Dm + h * DKk;
    const float* inv0 = inv + (size_t)bh * Sseq;
    float* Cb = O + (size_t)b * Sseq * Dm + h * DKk;
    const int bm = blockIdx.x * 128;
    const int tid = threadIdx.x;
    const int warp = tid >> 5, lane = tid & 31;
    const int u = lane >> 2, cl = lane & 3;
    const int wm = (warp >> 2) * 64, wn = (warp & 3) * 24;
    float acc[4][3][4] = {};

    auto load_tile = [&](int t, int st) {
        const __nv_bfloat16* Ag = Ag0 + (size_t)(t * 32) * Sseq + bm;
        // A tile: 32 rows x 128 bf16 = 512 x 16B units, 2 per thread
        #pragma unroll
        for (int i = 0; i < 2; i++) {
            int f = tid + i * 256;
            int k = f >> 4, j = f & 15;            // 16 units (of 8 bf16) per row
            cp16((char*)(As + st * 2048) + (k * 16 + (j ^ (k & 7))) * 16,
                 Ag + (size_t)k * Sseq + j * 8);
        }
        const float* Bg = Bg0 + (size_t)(t * 32) * Dm;
        #pragma unroll
        for (int i = 0; i < 3; i++) {
            int f = tid + i * 256;
            int k = f / 24, c4 = (f % 24) << 2;
            cp16(&Bs[st * 3072 + k * 96 + (c4 ^ ((k & 3) << 3))], Bg + (size_t)k * Dm + c4);
        }
        if (tid < 8) cp16(&Is[st * 32 + tid * 4], inv0 + t * 32 + tid * 4);
    };

    load_tile(0, 0); CP_COMMIT();
    for (int t = 0; t < 32; t++) {
        if (t + 1 < 32) { load_tile(t + 1, (t + 1) & 1); CP_COMMIT(); CP_WAIT1(); }
        else CP_WAIT0();
        __syncthreads();
        const unsigned short* Ab = (const unsigned short*)(As + (t & 1) * 2048);
        const float* Bb = Bs + (t & 1) * 3072;
        const float* Ib = Is + (t & 1) * 32;
        #pragma unroll
        for (int kk = 0; kk < 32; kk += 8) {
            uint32_t af[4][4], bf[3][2];
            int k0 = kk + cl;
            float is0 = Ib[k0], is1 = Ib[k0 + 4];
            int s = (k0 & 3) << 3;
            #pragma unroll
            for (int mt = 0; mt < 4; mt++) {
                int r = wm + mt * 16 + u;        // q index
                int u0 = r >> 3, e0 = r & 7;
                int u1 = (r + 8) >> 3, e1 = r & 7;
                af[mt][0] = ((uint32_t)Ab[(k0 * 16 + (u0 ^ (k0 & 7))) * 8 + e0]) << 16;
                af[mt][1] = ((uint32_t)Ab[(k0 * 16 + (u1 ^ (k0 & 7))) * 8 + e1]) << 16;
                af[mt][2] = ((uint32_t)Ab[((k0 + 4) * 16 + (u0 ^ ((k0 + 4) & 7))) * 8 + e0]) << 16;
                af[mt][3] = ((uint32_t)Ab[((k0 + 4) * 16 + (u1 ^ ((k0 + 4) & 7))) * 8 + e1]) << 16;
            }
            #pragma unroll
            for (int nt = 0; nt < 3; nt++) {
                int n = wn + nt * 8 + u;
                bf[nt][0] = f2tf(Bb[k0 * 96 + (n ^ s)] * is0);
                bf[nt][1] = f2tf(Bb[(k0 + 4) * 96 + (n ^ s)] * is1);
            }
            #pragma unroll
            for (int mt = 0; mt < 4; mt++)
                #pragma unroll
                for (int nt = 0; nt < 3; nt++)
                    mma8(acc[mt][nt], af[mt], bf[nt]);
        }
        __syncthreads();
    }
    #pragma unroll
    for (int mt = 0; mt < 4; mt++) {
        #pragma unroll
        for (int nt = 0; nt < 3; nt++) {
            int q = bm + wm + mt * 16 + u;
            int c = wn + nt * 8 + 2 * cl;
            float2 v0, v1;
            v0.x = acc[mt][nt][0]; v0.y = acc[mt][nt][1];
            v1.x = acc[mt][nt][2]; v1.y = acc[mt][nt][3];
            *(float2*)(Cb + (size_t)q * Dm + c)       = v0;
            *(float2*)(Cb + (size_t)(q + 8) * Dm + c) = v1;
        }
    }
}

// ---------------- out = LayerNorm(o + xin) * g + b  (row = 768) -----------------
__global__ void __launch_bounds__(256) add_ln(
    const float* __restrict__ o, const float* __restrict__ xin,
    const float* __restrict__ g, const float* __restrict__ bb,
    float* __restrict__ out)
{
    const size_t base = (size_t)blockIdx.x * Dm;
    const int tid = threadIdx.x;
    float v0 = o[base+tid]       + xin[base+tid];
    float v1 = o[base+tid+256]   + xin[base+tid+256];
    float v2 = o[base+tid+512]   + xin[base+tid+512];
    float s = v0 + v1 + v2;
    float q = v0*v0 + v1*v1 + v2*v2;
    __shared__ float shs[8], shq[8];
    #pragma unroll
    for (int off = 16; off > 0; off >>= 1) {
        s += __shfl_xor_sync(0xffffffffu, s, off);
        q += __shfl_xor_sync(0xffffffffu, q, off);
    }
    if ((tid & 31) == 0) { shs[tid >> 5] = s; shq[tid >> 5] = q; }
    __syncthreads();
    s = 0.f; q = 0.f;
    #pragma unroll
    for (int i = 0; i < 8; i++) { s += shs[i]; q += shq[i]; }
    float mean = s * (1.0f / Dm);
    float var  = q * (1.0f / Dm) - mean * mean;
    float r = rsqrtf(var + 1e-5f);
    out[base+tid]     = (v0 - mean) * r * g[tid]     + bb[tid];
    out[base+tid+256] = (v1 - mean) * r * g[tid+256] + bb[tid+256];
    out[base+tid+512] = (v2 - mean) * r * g[tid+512] + bb[tid+512];
}

// -------------------------------- host orchestration ---------------------------
#define SMEM_GEMM  (16384 * 4)          // 64 KB
#define SMEM_OUT   (10304 * 4)          // ~41 KB

static void run_mha(const float* xin, float* xout,
                    const float* Wq, const float* bq,
                    const float* Wv, const float* bv,
                    const float* gg, const float* bb,
                    const int* mask,
                    float* q, float* kv, __nv_bfloat16* sc, float* o,
                    float* part, float* inv)
{
    gemm_proj2<<<dim3(Dm / 128, MR / 128, 2), 256, SMEM_GEMM>>>(xin, Wq, bq, q, Wv, bv, kv);
    scores_exp<<<dim3(8, 8, BHn), 256, SMEM_GEMM>>>(kv, q, mask, sc, part);
    rs_reduce_fix<<<BHn * Sseq / 256, 256>>>(part, inv, sc);
    out_tn_tf32<<<dim3(8, BHn), 256, SMEM_OUT>>>(sc, kv, inv, o);
    add_ln<<<MR, 256>>>(o, xin, gg, bb, xout);
}

extern "C" void kernel_launch(void* const* d_in, const int* in_sizes, int n_in,
                              void* d_out, int out_size)
{
    const float* x     = (const float*)d_in[0];
    const void*  maskr = d_in[1];
    const float* a1_Wq = (const float*)d_in[2];
    const float* a1_bq = (const float*)d_in[3];
    const float* a1_Wv = (const float*)d_in[4];
    const float* a1_bv = (const float*)d_in[5];
    const float* a1_g  = (const float*)d_in[6];
    const float* a1_b  = (const float*)d_in[7];
    const float* a2_Wq = (const float*)d_in[8];
    const float* a2_bq = (const float*)d_in[9];
    const float* a2_Wv = (const float*)d_in[10];
    const float* a2_bv = (const float*)d_in[11];
    const float* a2_g  = (const float*)d_in[12];
    const float* a2_b  = (const float*)d_in[13];
    const float* f_W1  = (const float*)d_in[14];
    const float* f_b1  = (const float*)d_in[15];
    const float* f_W2  = (const float*)d_in[16];
    const float* f_b2  = (const float*)d_in[17];
    const float* f_g   = (const float*)d_in[18];
    const float* f_b   = (const float*)d_in[19];

    static int attr_done = 0;
    if (!attr_done) {
        cudaFuncSetAttribute(gemm_nn_tf32, cudaFuncAttributeMaxDynamicSharedMemorySize, SMEM_GEMM);
        cudaFuncSetAttribute(gemm_proj2,   cudaFuncAttributeMaxDynamicSharedMemorySize, SMEM_GEMM);
        cudaFuncSetAttribute(scores_exp,   cudaFuncAttributeMaxDynamicSharedMemorySize, SMEM_GEMM);
        cudaFuncSetAttribute(out_tn_tf32,  cudaFuncAttributeMaxDynamicSharedMemorySize, SMEM_OUT);
        attr_done = 1;
    }

    float *q, *kv, *o, *hbuf, *x1, *x2, *part, *inv;
    __nv_bfloat16 *sc;
    int *mask;
    cudaGetSymbolAddress((void**)&q,    g_q);
    cudaGetSymbolAddress((void**)&kv,   g_kv);
    cudaGetSymbolAddress((void**)&sc,   g_sc);
    cudaGetSymbolAddress((void**)&o,    g_o);
    cudaGetSymbolAddress((void**)&hbuf, g_h);
    cudaGetSymbolAddress((void**)&x1,   g_x1);
    cudaGetSymbolAddress((void**)&x2,   g_x2);
    cudaGetSymbolAddress((void**)&mask, g_mask);
    cudaGetSymbolAddress((void**)&part, g_part);
    cudaGetSymbolAddress((void**)&inv,  g_inv);

    mask_norm<<<1, 1024>>>((const unsigned char*)maskr, mask);

    run_mha(x,  x1, a1_Wq, a1_bq, a1_Wv, a1_bv, a1_g, a1_b, mask, q, kv, sc, o, part, inv);
    run_mha(x1, x2, a2_Wq, a2_bq, a2_Wv, a2_bv, a2_g, a2_b, mask, q, kv, sc, o, part, inv);

    gemm_nn_tf32<<<dim3(FFm / 128, MR / 128), 256, SMEM_GEMM>>>(x2, f_W1, f_b1, hbuf, MR, FFm, Dm, 1);
    gemm_nn_tf32<<<dim3(Dm  / 128, MR / 128), 256, SMEM_GEMM>>>(hbuf, f_W2, f_b2, o,  MR, Dm, FFm, 0);
    add_ln<<<MR, 256>>>(o, x2, f_g, f_b, (float*)d_out);
}

// round 9
// speedup vs baseline: 3.3295x; 1.0449x over previous
#include <cuda_runtime.h>
#include <cuda_bf16.h>
#include <cstdint>

#define Dm    768
#define Hh    8
#define DKk   96
#define FFm   1024
#define Bbat  8
#define Sseq  1024
#define MR    (Bbat*Sseq)   // 8192 rows
#define BHn   (Bbat*Hh)     // 64 batch*head

// ---------------- scratch (device globals; no allocations allowed) -------------
__device__ float g_q [(size_t)MR*Dm];                   // Q, then V' (=V*inv_s)
__device__ float g_kv[(size_t)MR*Dm];
__device__ __nv_bfloat16 g_sc[(size_t)BHn*Sseq*Sseq];   // 134 MB, E[k,q] bf16
__device__ float g_o [(size_t)MR*Dm];
__device__ float g_h [(size_t)MR*FFm];                  // FFN hidden; aliased as x0 early
__device__ float g_x1[(size_t)MR*Dm];
__device__ float g_x2[(size_t)MR*Dm];
__device__ int   g_mask[MR];
__device__ float g_part[(size_t)BHn*Sseq*8];
__device__ float g_inv [(size_t)BHn*Sseq];
__device__ float g_w  [3932160];                        // rounded weights

#define W_Q1 0
#define W_V1 589824
#define W_Q2 1179648
#define W_V2 1769472
#define W_F1 2359296
#define W_F2 3145728

// ------------------------------- small helpers ---------------------------------
__device__ __forceinline__ uint32_t f2tf(float x) {
    uint32_t u;
    asm("cvt.rna.tf32.f32 %0, %1;" : "=r"(u) : "f"(x));
    return u;
}
__device__ __forceinline__ float rnd_tf(float x) { return __uint_as_float(f2tf(x)); }

__device__ __forceinline__ void mma8(float* c, const uint32_t* a, const uint32_t* b) {
    asm volatile(
        "mma.sync.aligned.m16n8k8.row.col.f32.tf32.tf32.f32 "
        "{%0,%1,%2,%3}, {%4,%5,%6,%7}, {%8,%9}, {%0,%1,%2,%3};\n"
        : "+f"(c[0]), "+f"(c[1]), "+f"(c[2]), "+f"(c[3])
        : "r"(a[0]), "r"(a[1]), "r"(a[2]), "r"(a[3]), "r"(b[0]), "r"(b[1]));
}

__device__ __forceinline__ void cp16(void* dst_smem, const void* src) {
    uint32_t d = (uint32_t)__cvta_generic_to_shared(dst_smem);
    asm volatile("cp.async.ca.shared.global [%0], [%1], 16;" :: "r"(d), "l"(src));
}
#define CP_COMMIT()  asm volatile("cp.async.commit_group;")
#define CP_WAIT1()   asm volatile("cp.async.wait_group 1;")
#define CP_WAIT0()   asm volatile("cp.async.wait_group 0;")

// ----------------------- round a buffer to tf32 (vectorized) --------------------
__global__ void round_buf(const float* __restrict__ in, float* __restrict__ out, int n4)
{
    int i = blockIdx.x * 256 + threadIdx.x;
    if (i < n4) {
        float4 v = ((const float4*)in)[i];
        v.x = rnd_tf(v.x); v.y = rnd_tf(v.y); v.z = rnd_tf(v.z); v.w = rnd_tf(v.w);
        ((float4*)out)[i] = v;
    }
}

// ------------- V' = tf32(V * inv_s[b,h,k]) ; element-parallel -------------------
__global__ void vscale(const float* __restrict__ kv, const float* __restrict__ inv,
                       float* __restrict__ vp)
{
    size_t i = ((size_t)blockIdx.x * 256 + threadIdx.x) * 4;   // 4 elems, same head
    int b = (int)(i / ((size_t)Sseq * Dm));
    int rem = (int)(i - (size_t)b * Sseq * Dm);
    int s = rem / Dm, d = rem % Dm;
    int h = d / DKk;
    float is = inv[(b * Hh + h) * Sseq + s];
    float4 v = *(const float4*)(kv + i);
    v.x = rnd_tf(v.x * is); v.y = rnd_tf(v.y * is);
    v.z = rnd_tf(v.z * is); v.w = rnd_tf(v.w * is);
    *(float4*)(vp + i) = v;
}

// --------- normalize attention_mask (handles int32 OR uint8 storage) -----------
__global__ void mask_norm(const unsigned char* __restrict__ raw, int* __restrict__ out)
{
    __shared__ int flag;
    if (threadIdx.x == 0) flag = 0;
    __syncthreads();
    int local = 0;
    for (int i = threadIdx.x; i < MR; i += blockDim.x)
        if ((i & 3) != 0 && raw[i]) local = 1;
    if (local) flag = 1;
    __syncthreads();
    if (flag) {
        for (int i = threadIdx.x; i < MR; i += blockDim.x)
            out[i] = raw[i] ? 1 : 0;
    } else {
        const int* r = (const int*)raw;
        for (int i = threadIdx.x; i < MR; i += blockDim.x)
            out[i] = r[i] ? 1 : 0;
    }
}

// ======== tf32 NN GEMM core (operands pre-rounded to tf32; NO inner cvt) ========
// mode: 0 plain, 1 relu+round, 2 round
__device__ __forceinline__ void gemm_core(
    float* sm, const float* A, const float* B,
    const float* bias, float* C, int M, int N, int K, int mode, int bm, int bn)
{
    float* As = sm;            // 2 * 4096, [m128][k32] swz (r&7)<<2
    float* Bs = sm + 8192;     // 2 * 4096, [k32][n128] swz (k&3)<<3
    const int tid = threadIdx.x;
    const int warp = tid >> 5, lane = tid & 31;
    const int u = lane >> 2, cl = lane & 3;
    const int wm = (warp >> 2) * 64, wn = (warp & 3) * 32;
    float acc[4][4][4] = {};
    const int ntile = K >> 5;

    auto load_tile = [&](int t, int st) {
        const float* Ag = A + (size_t)bm * K + t * 32;
        #pragma unroll
        for (int i = 0; i < 4; i++) {
            int f = tid + i * 256;
            int r = f >> 3, c4 = (f & 7) << 2;
            cp16(&As[st * 4096 + r * 32 + (c4 ^ ((r & 7) << 2))], Ag + (size_t)r * K + c4);
        }
        const float* Bg = B + (size_t)(t * 32) * N + bn;
        #pragma unroll
        for (int i = 0; i < 4; i++) {
            int f = tid + i * 256;
            int k = f >> 5, c4 = (f & 31) << 2;
            cp16(&Bs[st * 4096 + k * 128 + (c4 ^ ((k & 3) << 3))], Bg + (size_t)k * N + c4);
        }
    };

    load_tile(0, 0); CP_COMMIT();
    for (int t = 0; t < ntile; t++) {
        if (t + 1 < ntile) { load_tile(t + 1, (t + 1) & 1); CP_COMMIT(); CP_WAIT1(); }
        else CP_WAIT0();
        __syncthreads();
        const float* Ab = As + (t & 1) * 4096;
        const float* Bb = Bs + (t & 1) * 4096;
        #pragma unroll
        for (int kk = 0; kk < 32; kk += 8) {
            uint32_t af[4][4], bf[4][2];
            #pragma unroll
            for (int mt = 0; mt < 4; mt++) {
                int r = wm + mt * 16 + u;
                int s = (r & 7) << 2;
                af[mt][0] = __float_as_uint(Ab[r * 32 + ((kk + cl) ^ s)]);
                af[mt][1] = __float_as_uint(Ab[(r + 8) * 32 + ((kk + cl) ^ s)]);
                af[mt][2] = __float_as_uint(Ab[r * 32 + ((kk + 4 + cl) ^ s)]);
                af[mt][3] = __float_as_uint(Ab[(r + 8) * 32 + ((kk + 4 + cl) ^ s)]);
            }
            #pragma unroll
            for (int nt = 0; nt < 4; nt++) {
                int n = wn + nt * 8 + u;
                int k0 = kk + cl;
                int s = (k0 & 3) << 3;
                bf[nt][0] = __float_as_uint(Bb[k0 * 128 + (n ^ s)]);
                bf[nt][1] = __float_as_uint(Bb[(k0 + 4) * 128 + (n ^ s)]);
            }
            #pragma unroll
            for (int mt = 0; mt < 4; mt++)
                #pragma unroll
                for (int nt = 0; nt < 4; nt++)
                    mma8(acc[mt][nt], af[mt], bf[nt]);
        }
        __syncthreads();
    }
    #pragma unroll
    for (int mt = 0; mt < 4; mt++) {
        #pragma unroll
        for (int nt = 0; nt < 4; nt++) {
            int r = bm + wm + mt * 16 + u;
            int c = bn + wn + nt * 8 + 2 * cl;
            float bx = bias[c], by = bias[c + 1];
            float2 v0, v1;
            v0.x = acc[mt][nt][0] + bx; v0.y = acc[mt][nt][1] + by;
            v1.x = acc[mt][nt][2] + bx; v1.y = acc[mt][nt][3] + by;
            if (mode == 1) {
                v0.x = rnd_tf(fmaxf(v0.x, 0.f)); v0.y = rnd_tf(fmaxf(v0.y, 0.f));
                v1.x = rnd_tf(fmaxf(v1.x, 0.f)); v1.y = rnd_tf(fmaxf(v1.y, 0.f));
            } else if (mode == 2) {
                v0.x = rnd_tf(v0.x); v0.y = rnd_tf(v0.y);
                v1.x = rnd_tf(v1.x); v1.y = rnd_tf(v1.y);
            }
            *(float2*)(C + (size_t)r * N + c)       = v0;
            *(float2*)(C + (size_t)(r + 8) * N + c) = v1;
        }
    }
}

__global__ void __launch_bounds__(256) gemm_nn_tf32(
    const float* __restrict__ A, const float* __restrict__ B,
    const float* __restrict__ bias, float* __restrict__ C,
    int M, int N, int K, int mode)
{
    extern __shared__ float sm[];
    gemm_core(sm, A, B, bias, C, M, N, K, mode, blockIdx.y * 128, blockIdx.x * 128);
}

// fused Q + KV projection (z selects weight/bias/output), output tf32-rounded
__global__ void __launch_bounds__(256) gemm_proj2(
    const float* __restrict__ x,
    const float* __restrict__ Wq, const float* __restrict__ bq, float* __restrict__ q,
    const float* __restrict__ Wv, const float* __restrict__ bv, float* __restrict__ kv)
{
    extern __shared__ float sm[];
    const float* W = blockIdx.z ? Wv : Wq;
    const float* bb = blockIdx.z ? bv : bq;
    float* C = blockIdx.z ? kv : q;
    gemm_core(sm, x, W, bb, C, MR, Dm, Dm, 2, blockIdx.y * 128, blockIdx.x * 128);
}

// ===== scores: E[k,q] = bf16(exp(KV[k]·Q[q]/sqrt(DK))), masked->0, + row partials
__global__ void __launch_bounds__(256) scores_exp(
    const float* __restrict__ KVp, const float* __restrict__ Qp,
    const int* __restrict__ pad, __nv_bfloat16* __restrict__ Sc,
    float* __restrict__ part_out)
{
    extern __shared__ float sm[];
    float* As = sm;
    float* Bs = sm + 8192;
    const int bh = blockIdx.z;
    const int b = bh >> 3, h = bh & 7;
    const float* Ag0 = KVp + (size_t)b * Sseq * Dm + h * DKk;
    const float* Bg0 = Qp  + (size_t)b * Sseq * Dm + h * DKk;
    __nv_bfloat16* Cb = Sc + (size_t)bh * Sseq * Sseq;
    const int* padb = pad + b * Sseq;
    const int bm = blockIdx.y * 128;   // k rows
    const int bn = blockIdx.x * 128;   // q cols
    const int tid = threadIdx.x;
    const int warp = tid >> 5, lane = tid & 31;
    const int u = lane >> 2, cl = lane & 3;
    const int wm = (warp >> 2) * 64, wn = (warp & 3) * 32;
    float acc[4][4][4] = {};

    auto load_tile = [&](int t, int st) {
        const float* Ag = Ag0 + (size_t)bm * Dm + t * 32;
        const float* Bg = Bg0 + (size_t)bn * Dm + t * 32;
        #pragma unroll
        for (int i = 0; i < 4; i++) {
            int f = tid + i * 256;
            int r = f >> 3, c4 = (f & 7) << 2;
            int off = r * 32 + (c4 ^ ((r & 7) << 2));
            cp16(&As[st * 4096 + off], Ag + (size_t)r * Dm + c4);
            cp16(&Bs[st * 4096 + off], Bg + (size_t)r * Dm + c4);
        }
    };

    load_tile(0, 0); CP_COMMIT();
    for (int t = 0; t < 3; t++) {
        if (t + 1 < 3) { load_tile(t + 1, (t + 1) & 1); CP_COMMIT(); CP_WAIT1(); }
        else CP_WAIT0();
        __syncthreads();
        const float* Ab = As + (t & 1) * 4096;
        const float* Bb = Bs + (t & 1) * 4096;
        #pragma unroll
        for (int kk = 0; kk < 32; kk += 8) {
            uint32_t af[4][4], bf[4][2];
            #pragma unroll
            for (int mt = 0; mt < 4; mt++) {
                int r = wm + mt * 16 + u;
                int s = (r & 7) << 2;
                af[mt][0] = __float_as_uint(Ab[r * 32 + ((kk + cl) ^ s)]);
                af[mt][1] = __float_as_uint(Ab[(r + 8) * 32 + ((kk + cl) ^ s)]);
                af[mt][2] = __float_as_uint(Ab[r * 32 + ((kk + 4 + cl) ^ s)]);
                af[mt][3] = __float_as_uint(Ab[(r + 8) * 32 + ((kk + 4 + cl) ^ s)]);
            }
            #pragma unroll
            for (int nt = 0; nt < 4; nt++) {
                int q = wn + nt * 8 + u;
                int s = (q & 7) << 2;
                bf[nt][0] = __float_as_uint(Bb[q * 32 + ((kk + cl) ^ s)]);
                bf[nt][1] = __float_as_uint(Bb[q * 32 + ((kk + 4 + cl) ^ s)]);
            }
            #pragma unroll
            for (int mt = 0; mt < 4; mt++)
                #pragma unroll
                for (int nt = 0; nt < 4; nt++)
                    mma8(acc[mt][nt], af[mt], bf[nt]);
        }
        __syncthreads();
    }

    const float scale = 0.10206207261596577f;   // 1/sqrt(96)
    float rowsum[8] = {};
    #pragma unroll
    for (int mt = 0; mt < 4; mt++) {
        #pragma unroll
        for (int nt = 0; nt < 4; nt++) {
            int kr0 = bm + wm + mt * 16 + u;
            int q0  = bn + wn + nt * 8 + 2 * cl;
            int p0 = padb[q0], p1 = padb[q0 + 1];
            float e00 = (q0     < kr0     || p0) ? 0.f : __expf(acc[mt][nt][0] * scale);
            float e01 = (q0 + 1 < kr0     || p1) ? 0.f : __expf(acc[mt][nt][1] * scale);
            float e10 = (q0     < kr0 + 8 || p0) ? 0.f : __expf(acc[mt][nt][2] * scale);
            float e11 = (q0 + 1 < kr0 + 8 || p1) ? 0.f : __expf(acc[mt][nt][3] * scale);
            __nv_bfloat162 w0, w1;
            w0.x = __float2bfloat16(e00); w0.y = __float2bfloat16(e01);
            w1.x = __float2bfloat16(e10); w1.y = __float2bfloat16(e11);
            rowsum[mt * 2 + 0] += __bfloat162float(w0.x) + __bfloat162float(w0.y);
            rowsum[mt * 2 + 1] += __bfloat162float(w1.x) + __bfloat162float(w1.y);
            *(__nv_bfloat162*)(Cb + (size_t)kr0 * Sseq + q0)       = w0;
            *(__nv_bfloat162*)(Cb + (size_t)(kr0 + 8) * Sseq + q0) = w1;
        }
    }
    #pragma unroll
    for (int j = 0; j < 8; j++) {
        rowsum[j] += __shfl_xor_sync(0xffffffffu, rowsum[j], 1);
        rowsum[j] += __shfl_xor_sync(0xffffffffu, rowsum[j], 2);
    }
    float* part = sm;
    __syncthreads();
    if (cl == 0) {
        #pragma unroll
        for (int mt = 0; mt < 4; mt++) {
            int lr = wm + mt * 16 + u;
            part[(lr)     * 4 + (warp & 3)] = rowsum[mt * 2 + 0];
            part[(lr + 8) * 4 + (warp & 3)] = rowsum[mt * 2 + 1];
        }
    }
    __syncthreads();
    if (tid < 128) {
        float s = part[tid * 4] + part[tid * 4 + 1] + part[tid * 4 + 2] + part[tid * 4 + 3];
        part_out[((size_t)bh * Sseq + bm + tid) * 8 + blockIdx.x] = s;
    }
}

// ------ reduce partials -> inv_s; rewrite dead E rows to 1 (uniform softmax) ----
__global__ void __launch_bounds__(256) rs_reduce_fix(
    const float* __restrict__ part, float* __restrict__ inv, __nv_bfloat16* __restrict__ E)
{
    int i = blockIdx.x * 256 + threadIdx.x;
    float s = 0.f;
    #pragma unroll
    for (int j = 0; j < 8; j++) s += part[(size_t)i * 8 + j];
    if (s == 0.f) {
        inv[i] = 1.0f / 1024.0f;
        uint4* row = (uint4*)(E + (size_t)i * Sseq);
        uint4 ones = make_uint4(0x3F803F80u, 0x3F803F80u, 0x3F803F80u, 0x3F803F80u);
        for (int j = 0; j < Sseq / 8; j++) row[j] = ones;
    } else {
        inv[i] = 1.0f / s;
    }
}

// ========= O = E^T @ V' : block 128(q) x 96(dk), E bf16, V' pre-scaled ==========
__global__ void __launch_bounds__(256) out_tn_tf32(
    const __nv_bfloat16* __restrict__ Sc, const float* __restrict__ Vp,
    float* __restrict__ O)
{
    extern __shared__ float sm[];
    float* As = sm;            // 2 stages * 2048 floats (32k x 128q bf16, unit-swz)
    float* Bs = sm + 4096;     // 2 * 3072  ([k32][n96] swz (k&3)<<3)
    const int bh = blockIdx.y;
    const int b = bh >> 3, h = bh & 7;
    const __nv_bfloat16* Ag0 = Sc + (size_t)bh * Sseq * Sseq;
    const float* Bg0 = Vp + (size_t)b * Sseq * Dm + h * DKk;
    float* Cb = O + (size_t)b * Sseq * Dm + h * DKk;
    const int bm = blockIdx.x * 128;
    const int tid = threadIdx.x;
    const int warp = tid >> 5, lane = tid & 31;
    const int u = lane >> 2, cl = lane & 3;
    const int wm = (warp >> 2) * 64, wn = (warp & 3) * 24;
    float acc[4][3][4] = {};

    auto load_tile = [&](int t, int st) {
        const __nv_bfloat16* Ag = Ag0 + (size_t)(t * 32) * Sseq + bm;
        #pragma unroll
        for (int i = 0; i < 2; i++) {
            int f = tid + i * 256;
            int k = f >> 4, j = f & 15;
            cp16((char*)(As + st * 2048) + (k * 16 + (j ^ (k & 7))) * 16,
                 Ag + (size_t)k * Sseq + j * 8);
        }
        const float* Bg = Bg0 + (size_t)(t * 32) * Dm;
        #pragma unroll
        for (int i = 0; i < 3; i++) {
            int f = tid + i * 256;
            int k = f / 24, c4 = (f % 24) << 2;
            cp16(&Bs[st * 3072 + k * 96 + (c4 ^ ((k & 3) << 3))], Bg + (size_t)k * Dm + c4);
        }
    };

    load_tile(0, 0); CP_COMMIT();
    for (int t = 0; t < 32; t++) {
        if (t + 1 < 32) { load_tile(t + 1, (t + 1) & 1); CP_COMMIT(); CP_WAIT1(); }
        else CP_WAIT0();
        __syncthreads();
        const unsigned short* Ab = (const unsigned short*)(As + (t & 1) * 2048);
        const float* Bb = Bs + (t & 1) * 3072;
        #pragma unroll
        for (int kk = 0; kk < 32; kk += 8) {
            uint32_t af[4][4], bf[3][2];
            int k0 = kk + cl;
            int s = (k0 & 3) << 3;
            #pragma unroll
            for (int mt = 0; mt < 4; mt++) {
                int r = wm + mt * 16 + u;
                int u0 = r >> 3, e0 = r & 7;
                int u1 = (r + 8) >> 3, e1 = r & 7;
                af[mt][0] = ((uint32_t)Ab[(k0 * 16 + (u0 ^ (k0 & 7))) * 8 + e0]) << 16;
                af[mt][1] = ((uint32_t)Ab[(k0 * 16 + (u1 ^ (k0 & 7))) * 8 + e1]) << 16;
                af[mt][2] = ((uint32_t)Ab[((k0 + 4) * 16 + (u0 ^ ((k0 + 4) & 7))) * 8 + e0]) << 16;
                af[mt][3] = ((uint32_t)Ab[((k0 + 4) * 16 + (u1 ^ ((k0 + 4) & 7))) * 8 + e1]) << 16;
            }
            #pragma unroll
            for (int nt = 0; nt < 3; nt++) {
                int n = wn + nt * 8 + u;
                bf[nt][0] = __float_as_uint(Bb[k0 * 96 + (n ^ s)]);
                bf[nt][1] = __float_as_uint(Bb[(k0 + 4) * 96 + (n ^ s)]);
            }
            #pragma unroll
            for (int mt = 0; mt < 4; mt++)
                #pragma unroll
                for (int nt = 0; nt < 3; nt++)
                    mma8(acc[mt][nt], af[mt], bf[nt]);
        }
        __syncthreads();
    }
    #pragma unroll
    for (int mt = 0; mt < 4; mt++) {
        #pragma unroll
        for (int nt = 0; nt < 3; nt++) {
            int q = bm + wm + mt * 16 + u;
            int c = wn + nt * 8 + 2 * cl;
            float2 v0, v1;
            v0.x = acc[mt][nt][0]; v0.y = acc[mt][nt][1];
            v1.x = acc[mt][nt][2]; v1.y = acc[mt][nt][3];
            *(float2*)(Cb + (size_t)q * Dm + c)       = v0;
            *(float2*)(Cb + (size_t)(q + 8) * Dm + c) = v1;
        }
    }
}

// ------- out = LayerNorm(o + xin) * g + b  (row = 768); opt tf32-round ----------
__global__ void __launch_bounds__(256) add_ln(
    const float* __restrict__ o, const float* __restrict__ xin,
    const float* __restrict__ g, const float* __restrict__ bb,
    float* __restrict__ out, int rnd)
{
    const size_t base = (size_t)blockIdx.x * Dm;
    const int tid = threadIdx.x;
    float v0 = o[base+tid]       + xin[base+tid];
    float v1 = o[base+tid+256]   + xin[base+tid+256];
    float v2 = o[base+tid+512]   + xin[base+tid+512];
    float s = v0 + v1 + v2;
    float q = v0*v0 + v1*v1 + v2*v2;
    __shared__ float shs[8], shq[8];
    #pragma unroll
    for (int off = 16; off > 0; off >>= 1) {
        s += __shfl_xor_sync(0xffffffffu, s, off);
        q += __shfl_xor_sync(0xffffffffu, q, off);
    }
    if ((tid & 31) == 0) { shs[tid >> 5] = s; shq[tid >> 5] = q; }
    __syncthreads();
    s = 0.f; q = 0.f;
    #pragma unroll
    for (int i = 0; i < 8; i++) { s += shs[i]; q += shq[i]; }
    float mean = s * (1.0f / Dm);
    float var  = q * (1.0f / Dm) - mean * mean;
    float r = rsqrtf(var + 1e-5f);
    float o0 = (v0 - mean) * r * g[tid]     + bb[tid];
    float o1 = (v1 - mean) * r * g[tid+256] + bb[tid+256];
    float o2 = (v2 - mean) * r * g[tid+512] + bb[tid+512];
    if (rnd) { o0 = rnd_tf(o0); o1 = rnd_tf(o1); o2 = rnd_tf(o2); }
    out[base+tid]     = o0;
    out[base+tid+256] = o1;
    out[base+tid+512] = o2;
}

// -------------------------------- host orchestration ---------------------------
#define SMEM_GEMM  (16384 * 4)          // 64 KB
#define SMEM_OUT   (10240 * 4)          // 40 KB

static void run_mha(const float* xin_gemm, const float* xin_res, float* xout, int rnd_out,
                    const float* rWq, const float* bq,
                    const float* rWv, const float* bv,
                    const float* gg, const float* bb,
                    const int* mask,
                    float* q, float* kv, __nv_bfloat16* sc, float* o,
                    float* part, float* inv)
{
    gemm_proj2<<<dim3(Dm / 128, MR / 128, 2), 256, SMEM_GEMM>>>(xin_gemm, rWq, bq, q, rWv, bv, kv);
    scores_exp<<<dim3(8, 8, BHn), 256, SMEM_GEMM>>>(kv, q, mask, sc, part);
    rs_reduce_fix<<<BHn * Sseq / 256, 256>>>(part, inv, sc);
    vscale<<<MR * Dm / 1024, 256>>>(kv, inv, q);          // V' overwrites Q (done with it)
    out_tn_tf32<<<dim3(8, BHn), 256, SMEM_OUT>>>(sc, q, o);
    add_ln<<<MR, 256>>>(o, xin_res, gg, bb, xout, rnd_out);
}

extern "C" void kernel_launch(void* const* d_in, const int* in_sizes, int n_in,
                              void* d_out, int out_size)
{
    const float* x     = (const float*)d_in[0];
    const void*  maskr = d_in[1];
    const float* a1_Wq = (const float*)d_in[2];
    const float* a1_bq = (const float*)d_in[3];
    const float* a1_Wv = (const float*)d_in[4];
    const float* a1_bv = (const float*)d_in[5];
    const float* a1_g  = (const float*)d_in[6];
    const float* a1_b  = (const float*)d_in[7];
    const float* a2_Wq = (const float*)d_in[8];
    const float* a2_bq = (const float*)d_in[9];
    const float* a2_Wv = (const float*)d_in[10];
    const float* a2_bv = (const float*)d_in[11];
    const float* a2_g  = (const float*)d_in[12];
    const float* a2_b  = (const float*)d_in[13];
    const float* f_W1  = (const float*)d_in[14];
    const float* f_b1  = (const float*)d_in[15];
    const float* f_W2  = (const float*)d_in[16];
    const float* f_b2  = (const float*)d_in[17];
    const float* f_g   = (const float*)d_in[18];
    const float* f_b   = (const float*)d_in[19];

    static int attr_done = 0;
    if (!attr_done) {
        cudaFuncSetAttribute(gemm_nn_tf32, cudaFuncAttributeMaxDynamicSharedMemorySize, SMEM_GEMM);
        cudaFuncSetAttribute(gemm_proj2,   cudaFuncAttributeMaxDynamicSharedMemorySize, SMEM_GEMM);
        cudaFuncSetAttribute(scores_exp,   cudaFuncAttributeMaxDynamicSharedMemorySize, SMEM_GEMM);
        cudaFuncSetAttribute(out_tn_tf32,  cudaFuncAttributeMaxDynamicSharedMemorySize, SMEM_OUT);
        attr_done = 1;
    }

    float *q, *kv, *o, *hbuf, *x1, *x2, *part, *inv, *w;
    __nv_bfloat16 *sc;
    int *mask;
    cudaGetSymbolAddress((void**)&q,    g_q);
    cudaGetSymbolAddress((void**)&kv,   g_kv);
    cudaGetSymbolAddress((void**)&sc,   g_sc);
    cudaGetSymbolAddress((void**)&o,    g_o);
    cudaGetSymbolAddress((void**)&hbuf, g_h);
    cudaGetSymbolAddress((void**)&x1,   g_x1);
    cudaGetSymbolAddress((void**)&x2,   g_x2);
    cudaGetSymbolAddress((void**)&mask, g_mask);
    cudaGetSymbolAddress((void**)&part, g_part);
    cudaGetSymbolAddress((void**)&inv,  g_inv);
    cudaGetSymbolAddress((void**)&w,    g_w);

    mask_norm<<<1, 1024>>>((const unsigned char*)maskr, mask);

    // pre-round weights + layer-1 input (x0 aliases g_h, free until FFN)
    float* x0 = hbuf;
    const int NW = Dm * Dm / 4, NF = Dm * FFm / 4;
    round_buf<<<(MR * Dm / 4 + 255) / 256, 256>>>(x, x0, MR * Dm / 4);
    round_buf<<<(NW + 255) / 256, 256>>>(a1_Wq, w + W_Q1, NW);
    round_buf<<<(NW + 255) / 256, 256>>>(a1_Wv, w + W_V1, NW);
    round_buf<<<(NW + 255) / 256, 256>>>(a2_Wq, w + W_Q2, NW);
    round_buf<<<(NW + 255) / 256, 256>>>(a2_Wv, w + W_V2, NW);
    round_buf<<<(NF + 255) / 256, 256>>>(f_W1, w + W_F1, NF);
    round_buf<<<(NF + 255) / 256, 256>>>(f_W2, w + W_F2, NF);

    run_mha(x0, x,  x1, 1, w + W_Q1, a1_bq, w + W_V1, a1_bv, a1_g, a1_b, mask, q, kv, sc, o, part, inv);
    run_mha(x1, x1, x2, 1, w + W_Q2, a2_bq, w + W_V2, a2_bv, a2_g, a2_b, mask, q, kv, sc, o, part, inv);

    gemm_nn_tf32<<<dim3(FFm / 128, MR / 128), 256, SMEM_GEMM>>>(x2, w + W_F1, f_b1, hbuf, MR, FFm, Dm, 1);
    gemm_nn_tf32<<<dim3(Dm  / 128, MR / 128), 256, SMEM_GEMM>>>(hbuf, w + W_F2, f_b2, o,  MR, Dm, FFm, 0);
    add_ln<<<MR, 256>>>(o, x2, f_g, f_b, (float*)d_out, 0);
}